// round 2
// baseline (speedup 1.0000x reference)
#include <cuda_runtime.h>

#define NB   8
#define RR   256
#define IND  64
#define OUTD 64
#define MD   32
#define KXN  64

// ---------------- scratch (device globals; no allocations allowed) ----------
__device__ float g_XwR[NB*MD*RR*IND];     // [n][ky][h][i]  forward w-DFT (re)
__device__ float g_XwI[NB*MD*RR*IND];
__device__ float g_XmR[NB*MD*KXN*IND];    // [n][ky][kx][i] forward modes
__device__ float g_XmI[NB*MD*KXN*IND];
__device__ float g_OmR[NB*MD*KXN*OUTD];   // [n][ky][kx][o] mixed modes
__device__ float g_OmI[NB*MD*KXN*OUTD];
__device__ float g_Y1R[NB*RR*MD*OUTD];    // [n][h][ky][o]  after inverse h-DFT
__device__ float g_Y1I[NB*RR*MD*OUTD];
__device__ float2 g_tw[256];              // (cos, sin)(2*pi*k/256)

__global__ void k_init_tw() {
    int k = threadIdx.x;
    double a = 6.283185307179586476925286766559 * (double)k / 256.0;
    g_tw[k] = make_float2((float)cos(a), (float)sin(a));
}

// ---------------- K1: forward DFT along w (real -> complex, ky in [0,32)) ---
// block = (n,h). Xw[n,ky,h,i] = (1/256) * sum_w x[n,h,w,i] * e^{-2pi i ky w/256}
__global__ __launch_bounds__(256) void k1_fwd_w(const float* __restrict__ x) {
    extern __shared__ float xs[];                 // [256][64]
    __shared__ float2 tcs[256];
    const int t = threadIdx.x;
    tcs[t] = g_tw[t];
    const int b = blockIdx.x;
    const int n = b >> 8, h = b & 255;
    const float4* xp = reinterpret_cast<const float4*>(x + (size_t)(n*RR + h)*RR*IND);
    float4* xs4 = reinterpret_cast<float4*>(xs);
#pragma unroll
    for (int it = 0; it < 16; it++) xs4[t + 256*it] = xp[t + 256*it];
    __syncthreads();

    const int tx = t & 31, ty = t >> 5;           // tx -> i pair, ty -> ky group
    const int ky0 = ty * 4;
    float2 aR[4], aI[4];
#pragma unroll
    for (int k = 0; k < 4; k++) { aR[k] = make_float2(0.f,0.f); aI[k] = make_float2(0.f,0.f); }
    const float2* xs2 = reinterpret_cast<const float2*>(xs);
    for (int w = 0; w < RR; w++) {
        float2 xv = xs2[w*32 + tx];
        int p = (ky0 * w) & 255;
#pragma unroll
        for (int k = 0; k < 4; k++) {
            float2 cs = tcs[p];
            aR[k].x = fmaf( cs.x, xv.x, aR[k].x);
            aR[k].y = fmaf( cs.x, xv.y, aR[k].y);
            aI[k].x = fmaf(-cs.y, xv.x, aI[k].x);
            aI[k].y = fmaf(-cs.y, xv.y, aI[k].y);
            p = (p + w) & 255;
        }
    }
    const float sc = 1.f/256.f;   // forward ortho norm 1/sqrt(256*256)
#pragma unroll
    for (int k = 0; k < 4; k++) {
        int ky = ky0 + k;
        size_t o = (size_t)((n*MD + ky)*RR + h)*IND + 2*tx;
        reinterpret_cast<float2*>(g_XwR)[o>>1] = make_float2(aR[k].x*sc, aR[k].y*sc);
        reinterpret_cast<float2*>(g_XwI)[o>>1] = make_float2(aI[k].x*sc, aI[k].y*sc);
    }
}

// ---------------- K2: forward DFT along h (complex), kx in {0..31,224..255} -
// block = (n,ky,half). Xm[kx] = sum_h Xw[h] * e^{-2pi i kappa h /256}
__global__ __launch_bounds__(256) void k2_fwd_h() {
    __shared__ float sR[64*IND];
    __shared__ float sI[64*IND];
    __shared__ float2 tcs[256];
    const int t = threadIdx.x;
    tcs[t] = g_tw[t];
    const int b = blockIdx.x;
    const int half = b & 1, ky = (b >> 1) & 31, n = b >> 6;
    const float* baseR = g_XwR + (size_t)(n*MD + ky)*RR*IND;
    const float* baseI = g_XwI + (size_t)(n*MD + ky)*RR*IND;
    const int tx = t & 31, ty = t >> 5;
    const int j0 = half*32 + ty*4;                      // kx slot (0..63)
    const int kap0 = half ? (192 + j0) : j0;            // actual DFT row
    float2 aR[4], aI[4];
#pragma unroll
    for (int k = 0; k < 4; k++) { aR[k] = make_float2(0.f,0.f); aI[k] = make_float2(0.f,0.f); }

    for (int hc = 0; hc < RR; hc += 64) {
        __syncthreads();
        const float4* pR = reinterpret_cast<const float4*>(baseR + hc*IND);
        const float4* pI = reinterpret_cast<const float4*>(baseI + hc*IND);
#pragma unroll
        for (int it = 0; it < 4; it++) {
            reinterpret_cast<float4*>(sR)[t + 256*it] = pR[t + 256*it];
            reinterpret_cast<float4*>(sI)[t + 256*it] = pI[t + 256*it];
        }
        __syncthreads();
        for (int hh = 0; hh < 64; hh++) {
            const int h = hc + hh;
            float2 R = reinterpret_cast<const float2*>(sR)[hh*32 + tx];
            float2 I = reinterpret_cast<const float2*>(sI)[hh*32 + tx];
            int p = (kap0 * h) & 255;
#pragma unroll
            for (int k = 0; k < 4; k++) {
                float2 cs = tcs[p];
                // e^{-i th}*(R+iI): R' = cR + sI ; I' = cI - sR
                aR[k].x = fmaf(cs.x, R.x, fmaf( cs.y, I.x, aR[k].x));
                aR[k].y = fmaf(cs.x, R.y, fmaf( cs.y, I.y, aR[k].y));
                aI[k].x = fmaf(cs.x, I.x, fmaf(-cs.y, R.x, aI[k].x));
                aI[k].y = fmaf(cs.x, I.y, fmaf(-cs.y, R.y, aI[k].y));
                p = (p + h) & 255;
            }
        }
    }
#pragma unroll
    for (int k = 0; k < 4; k++) {
        int kx = j0 + k;
        size_t o = (size_t)((n*MD + ky)*KXN + kx)*IND + 2*tx;
        reinterpret_cast<float2*>(g_XmR)[o>>1] = aR[k];
        reinterpret_cast<float2*>(g_XmI)[o>>1] = aI[k];
    }
}

// ---------------- K3: per-mode complex channel mix (8x64x64) ----------------
// block = (kx,ky). out[n,o] = sum_i Xm[n,i] * W[i,o]  (complex)
__global__ __launch_bounds__(256) void k3_mix(const float* __restrict__ w0,
                                              const float* __restrict__ w1) {
    __shared__ float XsR[NB*IND], XsI[NB*IND];
    __shared__ float WsR[IND*OUTD], WsI[IND*OUTD];
    const int t = threadIdx.x;
    const int b = blockIdx.x;
    const int kx = b >> 5, ky = b & 31;
#pragma unroll
    for (int it = 0; it < 2; it++) {
        int idx = t + 256*it;                          // 512 = 8n * 64i
        int nn = idx >> 6, ii = idx & 63;
        size_t g = (size_t)((nn*MD + ky)*KXN + kx)*IND + ii;
        XsR[idx] = g_XmR[g];
        XsI[idx] = g_XmI[g];
    }
    const float* wp = (kx < MD) ? (w0 + (size_t)(kx*MD + ky)*IND*OUTD*2)
                                : (w1 + (size_t)((kx - MD)*MD + ky)*IND*OUTD*2);
    const float2* wp2 = reinterpret_cast<const float2*>(wp);
#pragma unroll
    for (int it = 0; it < 16; it++) {
        int idx = t + 256*it;                          // 4096 = 64i*64o
        float2 wv = wp2[idx];
        WsR[idx] = wv.x; WsI[idx] = wv.y;
    }
    __syncthreads();
    const int o = t & 63, n0 = t >> 6;                 // handles n0 and n0+4
    float r0 = 0.f, i0 = 0.f, r1 = 0.f, i1 = 0.f;
#pragma unroll 4
    for (int i = 0; i < IND; i++) {
        float wr = WsR[i*OUTD + o], wi = WsI[i*OUTD + o];
        float xr = XsR[n0*IND + i], xi = XsI[n0*IND + i];
        r0 = fmaf(xr, wr, fmaf(-xi, wi, r0));
        i0 = fmaf(xr, wi, fmaf( xi, wr, i0));
        xr = XsR[(n0+4)*IND + i]; xi = XsI[(n0+4)*IND + i];
        r1 = fmaf(xr, wr, fmaf(-xi, wi, r1));
        i1 = fmaf(xr, wi, fmaf( xi, wr, i1));
    }
    size_t g0 = (size_t)((n0*MD + ky)*KXN + kx)*OUTD + o;
    g_OmR[g0] = r0; g_OmI[g0] = i0;
    size_t g1 = (size_t)(((n0+4)*MD + ky)*KXN + kx)*OUTD + o;
    g_OmR[g1] = r1; g_OmI[g1] = i1;
}

// ---------------- K4: inverse DFT along h -----------------------------------
// block = (n,ky,grp). Y1[h] = fac * sum_kx Om[kx] * e^{+2pi i kappa h/256}
// fac = c_ky/256 (irfft Hermitian coeff + full inverse ortho norm)
__global__ __launch_bounds__(256) void k4_inv_h() {
    __shared__ float sR[KXN*OUTD], sI[KXN*OUTD];
    __shared__ float2 tcs[256];
    const int t = threadIdx.x;
    tcs[t] = g_tw[t];
    const int b = blockIdx.x;
    const int grp = b & 3, ky = (b >> 2) & 31, n = b >> 7;
    const float4* pR = reinterpret_cast<const float4*>(g_OmR + (size_t)(n*MD + ky)*KXN*OUTD);
    const float4* pI = reinterpret_cast<const float4*>(g_OmI + (size_t)(n*MD + ky)*KXN*OUTD);
#pragma unroll
    for (int it = 0; it < 4; it++) {
        reinterpret_cast<float4*>(sR)[t + 256*it] = pR[t + 256*it];
        reinterpret_cast<float4*>(sI)[t + 256*it] = pI[t + 256*it];
    }
    __syncthreads();
    const int tx = t & 31, ty = t >> 5;
    const int hbase = grp*64 + ty*8;
    float2 aR[8], aI[8];
#pragma unroll
    for (int j = 0; j < 8; j++) { aR[j] = make_float2(0.f,0.f); aI[j] = make_float2(0.f,0.f); }
    for (int kx = 0; kx < KXN; kx++) {
        float2 R = reinterpret_cast<const float2*>(sR)[kx*32 + tx];
        float2 I = reinterpret_cast<const float2*>(sI)[kx*32 + tx];
        const int kap = (kx < MD) ? kx : (192 + kx);
        int p = (kap * hbase) & 255;
        const int step = kap & 255;
#pragma unroll
        for (int j = 0; j < 8; j++) {
            float2 cs = tcs[p];
            // e^{+i th}*(R+iI): R' = cR - sI ; I' = cI + sR
            aR[j].x = fmaf(cs.x, R.x, fmaf(-cs.y, I.x, aR[j].x));
            aR[j].y = fmaf(cs.x, R.y, fmaf(-cs.y, I.y, aR[j].y));
            aI[j].x = fmaf(cs.x, I.x, fmaf( cs.y, R.x, aI[j].x));
            aI[j].y = fmaf(cs.x, I.y, fmaf( cs.y, R.y, aI[j].y));
            p = (p + step) & 255;
        }
    }
    const float fac = (ky == 0 ? 1.f : 2.f) * (1.f/256.f);
#pragma unroll
    for (int j = 0; j < 8; j++) {
        int h = hbase + j;
        size_t o = (size_t)((n*RR + h)*MD + ky)*OUTD + 2*tx;
        reinterpret_cast<float2*>(g_Y1R)[o>>1] = make_float2(aR[j].x*fac, aR[j].y*fac);
        reinterpret_cast<float2*>(g_Y1I)[o>>1] = make_float2(aI[j].x*fac, aI[j].y*fac);
    }
}

// ---------------- K5: inverse w synthesis + residual GEMM + SiLU ------------
// block = (n,h). y[w,o] = sum_ky (Y1R*cos - Y1I*sin) ; out = silu(y + x@rw + rb)
__global__ __launch_bounds__(256) void k5_inv_w(const float* __restrict__ x,
                                                const float* __restrict__ res_w,
                                                const float* __restrict__ res_b,
                                                float* __restrict__ out) {
    extern __shared__ float xs[];                 // [256][64]
    __shared__ float YsR[MD*OUTD], YsI[MD*OUTD];
    __shared__ float rw[IND*OUTD];
    __shared__ float rb[OUTD];
    __shared__ float2 tcs[256];
    const int t = threadIdx.x;
    tcs[t] = g_tw[t];
    const int b = blockIdx.x;
    const int n = b >> 8, h = b & 255;
    const float4* xp = reinterpret_cast<const float4*>(x + (size_t)(n*RR + h)*RR*IND);
    float4* xs4 = reinterpret_cast<float4*>(xs);
#pragma unroll
    for (int it = 0; it < 16; it++) xs4[t + 256*it] = xp[t + 256*it];
    const float4* yR4 = reinterpret_cast<const float4*>(g_Y1R + (size_t)(n*RR + h)*MD*OUTD);
    const float4* yI4 = reinterpret_cast<const float4*>(g_Y1I + (size_t)(n*RR + h)*MD*OUTD);
#pragma unroll
    for (int it = 0; it < 2; it++) {
        reinterpret_cast<float4*>(YsR)[t + 256*it] = yR4[t + 256*it];
        reinterpret_cast<float4*>(YsI)[t + 256*it] = yI4[t + 256*it];
    }
#pragma unroll
    for (int it = 0; it < 4; it++)
        reinterpret_cast<float4*>(rw)[t + 256*it] =
            reinterpret_cast<const float4*>(res_w)[t + 256*it];
    if (t < 64) rb[t] = res_b[t];
    __syncthreads();

    const int tx = t & 31, ty = t >> 5;
    const float2 rbv = reinterpret_cast<const float2*>(rb)[tx];
    for (int grp = 0; grp < 4; grp++) {
        const int wbase = grp*64 + ty*8;
        float2 a[8];
#pragma unroll
        for (int j = 0; j < 8; j++) a[j] = rbv;
        // residual: a[j] += sum_i x[w_j,i]*rw[i,o]
        for (int i = 0; i < IND; i++) {
            float2 rwv = reinterpret_cast<const float2*>(rw)[i*32 + tx];
#pragma unroll
            for (int j = 0; j < 8; j++) {
                float xv = xs[(wbase + j)*IND + i];
                a[j].x = fmaf(xv, rwv.x, a[j].x);
                a[j].y = fmaf(xv, rwv.y, a[j].y);
            }
        }
        // spectral synthesis
        for (int ky = 0; ky < MD; ky++) {
            float2 yR = reinterpret_cast<const float2*>(YsR)[ky*32 + tx];
            float2 yI = reinterpret_cast<const float2*>(YsI)[ky*32 + tx];
            int p = (ky * wbase) & 255;
#pragma unroll
            for (int j = 0; j < 8; j++) {
                float2 cs = tcs[p];
                a[j].x = fmaf(cs.x, yR.x, fmaf(-cs.y, yI.x, a[j].x));
                a[j].y = fmaf(cs.x, yR.y, fmaf(-cs.y, yI.y, a[j].y));
                p = (p + ky) & 255;
            }
        }
#pragma unroll
        for (int j = 0; j < 8; j++) {
            float2 v = a[j];
            v.x = v.x / (1.f + __expf(-v.x));
            v.y = v.y / (1.f + __expf(-v.y));
            size_t o = (size_t)((n*RR + h)*RR + (wbase + j))*OUTD + 2*tx;
            reinterpret_cast<float2*>(out)[o>>1] = v;
        }
    }
}

// ---------------- launch ----------------------------------------------------
extern "C" void kernel_launch(void* const* d_in, const int* in_sizes, int n_in,
                              void* d_out, int out_size) {
    const float* x   = (const float*)d_in[0];
    const float* w0  = (const float*)d_in[1];
    const float* w1  = (const float*)d_in[2];
    const float* rsw = (const float*)d_in[3];
    const float* rsb = (const float*)d_in[4];
    float* out = (float*)d_out;

    cudaFuncSetAttribute(k1_fwd_w, cudaFuncAttributeMaxDynamicSharedMemorySize, 65536);
    cudaFuncSetAttribute(k5_inv_w, cudaFuncAttributeMaxDynamicSharedMemorySize, 65536);

    k_init_tw<<<1, 256>>>();
    k1_fwd_w<<<NB*RR, 256, 65536>>>(x);
    k2_fwd_h<<<NB*MD*2, 256>>>();
    k3_mix<<<KXN*MD, 256>>>(w0, w1);
    k4_inv_h<<<NB*MD*4, 256>>>();
    k5_inv_w<<<NB*RR, 256, 65536>>>(x, rsw, rsb, out);
}

// round 3
// speedup vs baseline: 1.4891x; 1.4891x over previous
#include <cuda_runtime.h>

#define NB   8
#define RR   256
#define IND  64
#define OUTD 64
#define MD   32
#define KXN  64

typedef unsigned long long ull;

// ---------------- scratch (device globals; no allocations allowed) ----------
__device__ float g_XwR[NB*MD*RR*IND];     // [n][ky][h][i]  forward w-DFT (re)
__device__ float g_XwI[NB*MD*RR*IND];
__device__ float g_XmR[NB*MD*KXN*IND];    // [ky][kx][n][i] forward modes
__device__ float g_XmI[NB*MD*KXN*IND];
__device__ float g_OmR[NB*MD*KXN*OUTD];   // [n][ky][kx][o] mixed modes
__device__ float g_OmI[NB*MD*KXN*OUTD];
__device__ float g_Y1R[NB*RR*MD*OUTD];    // [n][h][ky][o]  after inverse h-DFT
__device__ float g_Y1I[NB*RR*MD*OUTD];
__device__ float4 g_tw4p[256];            // (c, c,  s,  s)
__device__ float4 g_tw4n[256];            // (c, c, -s, -s)

// ---------------- packed f32x2 helpers --------------------------------------
__device__ __forceinline__ void fma2(ull &d, ull a, ull b) {
    asm("fma.rn.f32x2 %0, %1, %2, %0;" : "+l"(d) : "l"(a), "l"(b));
}
__device__ __forceinline__ ull splat2(float x) {
    ull r; asm("mov.b64 %0, {%1, %1};" : "=l"(r) : "f"(x)); return r;
}
__device__ __forceinline__ ull neg2(ull a, ull negone) {
    ull r; asm("mul.rn.f32x2 %0, %1, %2;" : "=l"(r) : "l"(a), "l"(negone)); return r;
}
__device__ __forceinline__ float2 unpk(ull v) {
    float2 r; asm("mov.b64 {%0, %1}, %2;" : "=f"(r.x), "=f"(r.y) : "l"(v)); return r;
}

__global__ void k_init_tw() {
    int k = threadIdx.x;
    double a = 6.283185307179586476925286766559 * (double)k / 256.0;
    float c = (float)cos(a), s = (float)sin(a);
    g_tw4p[k] = make_float4(c, c,  s,  s);
    g_tw4n[k] = make_float4(c, c, -s, -s);
}

// ---------------- K1: forward DFT along w (real -> complex, ky in [0,32)) ---
// block=(n,h), 128 thr, tile 4ky x 4i.  Xw = (1/256) sum_w x * (cos - i sin)
__global__ __launch_bounds__(128) void k1_fwd_w(const float* __restrict__ x) {
    extern __shared__ __align__(16) float xs[];       // [256][64]
    __shared__ __align__(16) float4 tws[256];         // (c,c,-s,-s)
    const int t = threadIdx.x;
    tws[t] = g_tw4n[t]; tws[t + 128] = g_tw4n[t + 128];
    const int b = blockIdx.x, n = b >> 8, h = b & 255;
    const float4* xp = reinterpret_cast<const float4*>(x + (size_t)(n*RR + h)*RR*IND);
    float4* xs4 = reinterpret_cast<float4*>(xs);
#pragma unroll
    for (int it = 0; it < 32; it++) xs4[t + 128*it] = xp[t + 128*it];
    __syncthreads();

    const int i0 = (t & 15) * 4, ky0 = (t >> 4) * 4;
    ull aR[4][2], aI[4][2];
#pragma unroll
    for (int k = 0; k < 4; k++) { aR[k][0]=aR[k][1]=aI[k][0]=aI[k][1]=0ull; }
    int p[4] = {0, 0, 0, 0};
    for (int w = 0; w < RR; w++) {
        ulonglong2 xv = *reinterpret_cast<const ulonglong2*>(&xs[w*IND + i0]);
#pragma unroll
        for (int k = 0; k < 4; k++) {
            ulonglong2 t4 = *reinterpret_cast<const ulonglong2*>(&tws[p[k]]);
            fma2(aR[k][0], t4.x, xv.x); fma2(aR[k][1], t4.x, xv.y);
            fma2(aI[k][0], t4.y, xv.x); fma2(aI[k][1], t4.y, xv.y);
            p[k] = (p[k] + ky0 + k) & 255;
        }
    }
    const float sc = 1.f/256.f;
#pragma unroll
    for (int k = 0; k < 4; k++) {
        size_t o = (size_t)((n*MD + ky0 + k)*RR + h)*IND + i0;
        float2 a0 = unpk(aR[k][0]), a1 = unpk(aR[k][1]);
        *reinterpret_cast<float4*>(&g_XwR[o]) = make_float4(a0.x*sc, a0.y*sc, a1.x*sc, a1.y*sc);
        a0 = unpk(aI[k][0]); a1 = unpk(aI[k][1]);
        *reinterpret_cast<float4*>(&g_XwI[o]) = make_float4(a0.x*sc, a0.y*sc, a1.x*sc, a1.y*sc);
    }
}

// ---------------- K2: forward DFT along h (complex), kx in {0..31,224..255} -
// block=(n,ky,half), 256 thr, tile 2kx x 4i.  R' = cR + sI ; I' = cI - sR
__global__ __launch_bounds__(256) void k2_fwd_h() {
    __shared__ __align__(16) float sR[64*IND], sI[64*IND];
    __shared__ __align__(16) float4 tws[256];         // (c,c,s,s)
    const int t = threadIdx.x;
    tws[t] = g_tw4p[t];
    const int b = blockIdx.x, half = b & 1, ky = (b >> 1) & 31, n = b >> 6;
    const float* baseR = g_XwR + (size_t)(n*MD + ky)*RR*IND;
    const float* baseI = g_XwI + (size_t)(n*MD + ky)*RR*IND;
    const int i0 = (t & 15) * 4, kxl = (t >> 4) * 2;
    const int kap0 = half ? (224 + kxl) : kxl;
    ull aR[2][2], aI[2][2];
    aR[0][0]=aR[0][1]=aR[1][0]=aR[1][1]=0ull;
    aI[0][0]=aI[0][1]=aI[1][0]=aI[1][1]=0ull;
    int p0 = 0, p1 = 0;
    const ull NEG1 = splat2(-1.f);
    for (int hc = 0; hc < RR; hc += 64) {
        __syncthreads();
        const float4* pR = reinterpret_cast<const float4*>(baseR + hc*IND);
        const float4* pI = reinterpret_cast<const float4*>(baseI + hc*IND);
#pragma unroll
        for (int it = 0; it < 4; it++) {
            reinterpret_cast<float4*>(sR)[t + 256*it] = pR[t + 256*it];
            reinterpret_cast<float4*>(sI)[t + 256*it] = pI[t + 256*it];
        }
        __syncthreads();
        for (int hh = 0; hh < 64; hh++) {
            ulonglong2 Rp = *reinterpret_cast<const ulonglong2*>(&sR[hh*IND + i0]);
            ulonglong2 Ip = *reinterpret_cast<const ulonglong2*>(&sI[hh*IND + i0]);
            ull Rn0 = neg2(Rp.x, NEG1), Rn1 = neg2(Rp.y, NEG1);
            ulonglong2 t4 = *reinterpret_cast<const ulonglong2*>(&tws[p0]);
            fma2(aR[0][0], t4.x, Rp.x); fma2(aR[0][0], t4.y, Ip.x);
            fma2(aR[0][1], t4.x, Rp.y); fma2(aR[0][1], t4.y, Ip.y);
            fma2(aI[0][0], t4.x, Ip.x); fma2(aI[0][0], t4.y, Rn0);
            fma2(aI[0][1], t4.x, Ip.y); fma2(aI[0][1], t4.y, Rn1);
            p0 = (p0 + kap0) & 255;
            t4 = *reinterpret_cast<const ulonglong2*>(&tws[p1]);
            fma2(aR[1][0], t4.x, Rp.x); fma2(aR[1][0], t4.y, Ip.x);
            fma2(aR[1][1], t4.x, Rp.y); fma2(aR[1][1], t4.y, Ip.y);
            fma2(aI[1][0], t4.x, Ip.x); fma2(aI[1][0], t4.y, Rn0);
            fma2(aI[1][1], t4.x, Ip.y); fma2(aI[1][1], t4.y, Rn1);
            p1 = (p1 + kap0 + 1) & 255;
        }
    }
#pragma unroll
    for (int kk = 0; kk < 2; kk++) {
        int kxs = half*32 + kxl + kk;
        size_t o = (size_t)((ky*KXN + kxs)*NB + n)*IND + i0;
        float2 a0 = unpk(aR[kk][0]), a1 = unpk(aR[kk][1]);
        *reinterpret_cast<float4*>(&g_XmR[o]) = make_float4(a0.x, a0.y, a1.x, a1.y);
        a0 = unpk(aI[kk][0]); a1 = unpk(aI[kk][1]);
        *reinterpret_cast<float4*>(&g_XmI[o]) = make_float4(a0.x, a0.y, a1.x, a1.y);
    }
}

// ---------------- K3: per-mode complex channel mix (8x64x64) ----------------
// block=(kx,ky). Weights streamed straight from global (coalesced per warp).
__global__ __launch_bounds__(256) void k3_mix(const float* __restrict__ w0,
                                              const float* __restrict__ w1) {
    __shared__ float XsR[NB*IND], XsI[NB*IND];
    const int t = threadIdx.x, b = blockIdx.x;
    const int kx = b >> 5, ky = b & 31;
    size_t xb = (size_t)(ky*KXN + kx)*NB*IND;
    XsR[t] = g_XmR[xb + t]; XsR[t + 256] = g_XmR[xb + t + 256];
    XsI[t] = g_XmI[xb + t]; XsI[t + 256] = g_XmI[xb + t + 256];
    __syncthreads();
    const float2* wp = reinterpret_cast<const float2*>(
        (kx < MD) ? (w0 + (size_t)(kx*MD + ky)*IND*OUTD*2)
                  : (w1 + (size_t)((kx - MD)*MD + ky)*IND*OUTD*2));
    const int o = t & 63, n0 = t >> 6;
    float r0 = 0.f, i0 = 0.f, r1 = 0.f, i1 = 0.f;
#pragma unroll 8
    for (int i = 0; i < IND; i++) {
        float2 wv = wp[i*OUTD + o];
        float xr = XsR[n0*IND + i], xi = XsI[n0*IND + i];
        r0 = fmaf(xr, wv.x, fmaf(-xi, wv.y, r0));
        i0 = fmaf(xr, wv.y, fmaf( xi, wv.x, i0));
        xr = XsR[(n0+4)*IND + i]; xi = XsI[(n0+4)*IND + i];
        r1 = fmaf(xr, wv.x, fmaf(-xi, wv.y, r1));
        i1 = fmaf(xr, wv.y, fmaf( xi, wv.x, i1));
    }
    size_t g0 = (size_t)((n0*MD + ky)*KXN + kx)*OUTD + o;
    g_OmR[g0] = r0; g_OmI[g0] = i0;
    size_t g1 = (size_t)(((n0+4)*MD + ky)*KXN + kx)*OUTD + o;
    g_OmR[g1] = r1; g_OmI[g1] = i1;
}

// ---------------- K4: inverse DFT along h -----------------------------------
// block=(n,ky,grp), tile 4h x 4o.  R' = cR - sI ; I' = cI + sR ; fac at store
__global__ __launch_bounds__(256) void k4_inv_h() {
    __shared__ __align__(16) float sR[KXN*OUTD], sI[KXN*OUTD];
    __shared__ __align__(16) float4 tws[256];         // (c,c,s,s)
    const int t = threadIdx.x;
    tws[t] = g_tw4p[t];
    const int b = blockIdx.x, grp = b & 3, ky = (b >> 2) & 31, n = b >> 7;
    const float4* pR = reinterpret_cast<const float4*>(g_OmR + (size_t)(n*MD + ky)*KXN*OUTD);
    const float4* pI = reinterpret_cast<const float4*>(g_OmI + (size_t)(n*MD + ky)*KXN*OUTD);
#pragma unroll
    for (int it = 0; it < 4; it++) {
        reinterpret_cast<float4*>(sR)[t + 256*it] = pR[t + 256*it];
        reinterpret_cast<float4*>(sI)[t + 256*it] = pI[t + 256*it];
    }
    __syncthreads();
    const int o0 = (t & 15) * 4, hG = t >> 4;
    int hj[4];
#pragma unroll
    for (int j = 0; j < 4; j++) hj[j] = grp*64 + hG*4 + j;
    ull aR[4][2], aI[4][2];
#pragma unroll
    for (int j = 0; j < 4; j++) { aR[j][0]=aR[j][1]=aI[j][0]=aI[j][1]=0ull; }
    const ull NEG1 = splat2(-1.f);
#pragma unroll 1
    for (int kh = 0; kh < 2; kh++) {
        const int kapb = kh ? 224 : 0;
        int p[4];
#pragma unroll
        for (int j = 0; j < 4; j++) p[j] = (kapb * hj[j]) & 255;
        for (int kk = 0; kk < 32; kk++) {
            const int kx = kh*32 + kk;
            ulonglong2 Rp = *reinterpret_cast<const ulonglong2*>(&sR[kx*OUTD + o0]);
            ulonglong2 Ip = *reinterpret_cast<const ulonglong2*>(&sI[kx*OUTD + o0]);
            ull In0 = neg2(Ip.x, NEG1), In1 = neg2(Ip.y, NEG1);
#pragma unroll
            for (int j = 0; j < 4; j++) {
                ulonglong2 t4 = *reinterpret_cast<const ulonglong2*>(&tws[p[j]]);
                fma2(aR[j][0], t4.x, Rp.x); fma2(aR[j][0], t4.y, In0);
                fma2(aR[j][1], t4.x, Rp.y); fma2(aR[j][1], t4.y, In1);
                fma2(aI[j][0], t4.x, Ip.x); fma2(aI[j][0], t4.y, Rp.x);
                fma2(aI[j][1], t4.x, Ip.y); fma2(aI[j][1], t4.y, Rp.y);
                p[j] = (p[j] + hj[j]) & 255;
            }
        }
    }
    const float fac = (ky == 0 ? 1.f : 2.f) * (1.f/256.f);
#pragma unroll
    for (int j = 0; j < 4; j++) {
        size_t o = (size_t)((n*RR + hj[j])*MD + ky)*OUTD + o0;
        float2 a0 = unpk(aR[j][0]), a1 = unpk(aR[j][1]);
        *reinterpret_cast<float4*>(&g_Y1R[o]) = make_float4(a0.x*fac, a0.y*fac, a1.x*fac, a1.y*fac);
        a0 = unpk(aI[j][0]); a1 = unpk(aI[j][1]);
        *reinterpret_cast<float4*>(&g_Y1I[o]) = make_float4(a0.x*fac, a0.y*fac, a1.x*fac, a1.y*fac);
    }
}

// ---------------- K5: inverse w synthesis + residual GEMM + SiLU ------------
// block=(n,h), tile 4w x 16o.  y = sum_ky (YR cos - YI sin); out = silu(y + x@rw + rb)
#define XPAD 68
__global__ __launch_bounds__(256) void k5_inv_w(const float* __restrict__ x,
                                                const float* __restrict__ res_w,
                                                const float* __restrict__ res_b,
                                                float* __restrict__ out) {
    extern __shared__ __align__(16) float xs[];       // [256][68] padded
    __shared__ __align__(16) float YsR[MD*OUTD], YsI[MD*OUTD];
    __shared__ __align__(16) float rws[IND*OUTD];
    __shared__ __align__(16) float4 tws[256];         // (c,c,-s,-s)
    __shared__ __align__(16) float rbs[64];
    const int t = threadIdx.x, b = blockIdx.x, n = b >> 8, h = b & 255;
    tws[t] = g_tw4n[t];
    const float4* xp = reinterpret_cast<const float4*>(x + (size_t)(n*RR + h)*RR*IND);
#pragma unroll
    for (int it = 0; it < 16; it++) {
        int j = t + 256*it;
        float4 v = xp[j];
        int w = j >> 4, c = j & 15;
        *reinterpret_cast<float4*>(&xs[w*XPAD + c*4]) = v;
    }
    const float4* yR4 = reinterpret_cast<const float4*>(g_Y1R + (size_t)(n*RR + h)*MD*OUTD);
    const float4* yI4 = reinterpret_cast<const float4*>(g_Y1I + (size_t)(n*RR + h)*MD*OUTD);
#pragma unroll
    for (int it = 0; it < 2; it++) {
        reinterpret_cast<float4*>(YsR)[t + 256*it] = yR4[t + 256*it];
        reinterpret_cast<float4*>(YsI)[t + 256*it] = yI4[t + 256*it];
    }
#pragma unroll
    for (int it = 0; it < 4; it++)
        reinterpret_cast<float4*>(rws)[t + 256*it] =
            reinterpret_cast<const float4*>(res_w)[t + 256*it];
    if (t < 64) rbs[t] = res_b[t];
    __syncthreads();

    const int o0 = (t & 3) * 16, wb = (t >> 2) * 4;
    ull acc[4][8];
    {
        ulonglong2 b01 = *reinterpret_cast<const ulonglong2*>(&rbs[o0]);
        ulonglong2 b23 = *reinterpret_cast<const ulonglong2*>(&rbs[o0 + 4]);
        ulonglong2 b45 = *reinterpret_cast<const ulonglong2*>(&rbs[o0 + 8]);
        ulonglong2 b67 = *reinterpret_cast<const ulonglong2*>(&rbs[o0 + 12]);
#pragma unroll
        for (int j = 0; j < 4; j++) {
            acc[j][0]=b01.x; acc[j][1]=b01.y; acc[j][2]=b23.x; acc[j][3]=b23.y;
            acc[j][4]=b45.x; acc[j][5]=b45.y; acc[j][6]=b67.x; acc[j][7]=b67.y;
        }
    }
    // residual GEMM
    for (int i = 0; i < IND; i++) {
        ulonglong2 r01 = *reinterpret_cast<const ulonglong2*>(&rws[i*OUTD + o0]);
        ulonglong2 r23 = *reinterpret_cast<const ulonglong2*>(&rws[i*OUTD + o0 + 4]);
        ulonglong2 r45 = *reinterpret_cast<const ulonglong2*>(&rws[i*OUTD + o0 + 8]);
        ulonglong2 r67 = *reinterpret_cast<const ulonglong2*>(&rws[i*OUTD + o0 + 12]);
#pragma unroll
        for (int j = 0; j < 4; j++) {
            ull sx = splat2(xs[(wb + j)*XPAD + i]);
            fma2(acc[j][0], sx, r01.x); fma2(acc[j][1], sx, r01.y);
            fma2(acc[j][2], sx, r23.x); fma2(acc[j][3], sx, r23.y);
            fma2(acc[j][4], sx, r45.x); fma2(acc[j][5], sx, r45.y);
            fma2(acc[j][6], sx, r67.x); fma2(acc[j][7], sx, r67.y);
        }
    }
    // spectral synthesis
    int p[4] = {0, 0, 0, 0};
    for (int ky = 0; ky < MD; ky++) {
        ulonglong2 yr01 = *reinterpret_cast<const ulonglong2*>(&YsR[ky*OUTD + o0]);
        ulonglong2 yr23 = *reinterpret_cast<const ulonglong2*>(&YsR[ky*OUTD + o0 + 4]);
        ulonglong2 yr45 = *reinterpret_cast<const ulonglong2*>(&YsR[ky*OUTD + o0 + 8]);
        ulonglong2 yr67 = *reinterpret_cast<const ulonglong2*>(&YsR[ky*OUTD + o0 + 12]);
        ulonglong2 yi01 = *reinterpret_cast<const ulonglong2*>(&YsI[ky*OUTD + o0]);
        ulonglong2 yi23 = *reinterpret_cast<const ulonglong2*>(&YsI[ky*OUTD + o0 + 4]);
        ulonglong2 yi45 = *reinterpret_cast<const ulonglong2*>(&YsI[ky*OUTD + o0 + 8]);
        ulonglong2 yi67 = *reinterpret_cast<const ulonglong2*>(&YsI[ky*OUTD + o0 + 12]);
#pragma unroll
        for (int j = 0; j < 4; j++) {
            ulonglong2 t4 = *reinterpret_cast<const ulonglong2*>(&tws[p[j]]);
            fma2(acc[j][0], t4.x, yr01.x); fma2(acc[j][0], t4.y, yi01.x);
            fma2(acc[j][1], t4.x, yr01.y); fma2(acc[j][1], t4.y, yi01.y);
            fma2(acc[j][2], t4.x, yr23.x); fma2(acc[j][2], t4.y, yi23.x);
            fma2(acc[j][3], t4.x, yr23.y); fma2(acc[j][3], t4.y, yi23.y);
            fma2(acc[j][4], t4.x, yr45.x); fma2(acc[j][4], t4.y, yi45.x);
            fma2(acc[j][5], t4.x, yr45.y); fma2(acc[j][5], t4.y, yi45.y);
            fma2(acc[j][6], t4.x, yr67.x); fma2(acc[j][6], t4.y, yi67.x);
            fma2(acc[j][7], t4.x, yr67.y); fma2(acc[j][7], t4.y, yi67.y);
            p[j] = (p[j] + wb + j) & 255;
        }
    }
    // epilogue: SiLU + store
#pragma unroll
    for (int j = 0; j < 4; j++) {
        float4 v4[4];
#pragma unroll
        for (int c = 0; c < 8; c++) {
            float2 v = unpk(acc[j][c]);
            v.x = v.x / (1.f + __expf(-v.x));
            v.y = v.y / (1.f + __expf(-v.y));
            reinterpret_cast<float2*>(v4)[c] = v;
        }
        size_t o = (size_t)((n*RR + h)*RR + wb + j)*OUTD + o0;
#pragma unroll
        for (int c = 0; c < 4; c++)
            *reinterpret_cast<float4*>(&out[o + 4*c]) = v4[c];
    }
}

// ---------------- launch ----------------------------------------------------
extern "C" void kernel_launch(void* const* d_in, const int* in_sizes, int n_in,
                              void* d_out, int out_size) {
    const float* x   = (const float*)d_in[0];
    const float* w0  = (const float*)d_in[1];
    const float* w1  = (const float*)d_in[2];
    const float* rsw = (const float*)d_in[3];
    const float* rsb = (const float*)d_in[4];
    float* out = (float*)d_out;

    cudaFuncSetAttribute(k1_fwd_w, cudaFuncAttributeMaxDynamicSharedMemorySize, 65536);
    cudaFuncSetAttribute(k5_inv_w, cudaFuncAttributeMaxDynamicSharedMemorySize, RR*XPAD*4);

    k_init_tw<<<1, 256>>>();
    k1_fwd_w<<<NB*RR, 128, 65536>>>(x);
    k2_fwd_h<<<NB*MD*2, 256>>>();
    k3_mix<<<KXN*MD, 256>>>(w0, w1);
    k4_inv_h<<<NB*MD*4, 256>>>();
    k5_inv_w<<<NB*RR, 256, RR*XPAD*4>>>(x, rsw, rsb, out);
}

// round 5
// speedup vs baseline: 2.0177x; 1.3550x over previous
#include <cuda_runtime.h>

#define NB   8
#define RR   256
#define IND  64
#define OUTD 64
#define MD   32
#define KXN  64

typedef unsigned long long ull;

// ---------------- scratch (device globals; no allocations allowed) ----------
__device__ float g_XwR[NB*MD*RR*IND];     // [n][ky][h][i]  forward w-DFT (re)
__device__ float g_XwI[NB*MD*RR*IND];
__device__ float g_XmR[NB*MD*KXN*IND];    // [ky][kx][n][i] forward modes
__device__ float g_XmI[NB*MD*KXN*IND];
__device__ float g_OmR[NB*MD*KXN*OUTD];   // [n][ky][kx][o] mixed modes
__device__ float g_OmI[NB*MD*KXN*OUTD];
__device__ float g_Y1R[NB*RR*MD*OUTD];    // [n][h][ky][o]  after inverse h-DFT
__device__ float g_Y1I[NB*RR*MD*OUTD];
__device__ float4 g_tw4p[256];            // (c, c,  s,  s)
__device__ float4 g_tw4n[256];            // (c, c, -s, -s)

// ---------------- packed f32x2 helpers --------------------------------------
__device__ __forceinline__ void fma2(ull &d, ull a, ull b) {
    asm("fma.rn.f32x2 %0, %1, %2, %0;" : "+l"(d) : "l"(a), "l"(b));
}
__device__ __forceinline__ ull splat2(float x) {
    ull r; asm("mov.b64 %0, {%1, %1};" : "=l"(r) : "f"(x)); return r;
}
__device__ __forceinline__ ull neg2(ull a, ull negone) {
    ull r; asm("mul.rn.f32x2 %0, %1, %2;" : "=l"(r) : "l"(a), "l"(negone)); return r;
}
__device__ __forceinline__ ull add2(ull a, ull b) {
    ull r; asm("add.rn.f32x2 %0, %1, %2;" : "=l"(r) : "l"(a), "l"(b)); return r;
}
__device__ __forceinline__ ull sub2(ull a, ull b, ull negone) {   // a - b
    ull r; asm("fma.rn.f32x2 %0, %1, %2, %3;" : "=l"(r) : "l"(b), "l"(negone), "l"(a)); return r;
}
__device__ __forceinline__ float2 unpk(ull v) {
    float2 r; asm("mov.b64 {%0, %1}, %2;" : "=f"(r.x), "=f"(r.y) : "l"(v)); return r;
}

__global__ void k_init_tw() {
    int k = threadIdx.x;
    double a = 6.283185307179586476925286766559 * (double)k / 256.0;
    float c = (float)cos(a), s = (float)sin(a);
    g_tw4p[k] = make_float4(c, c,  s,  s);
    g_tw4n[k] = make_float4(c, c, -s, -s);
}

// ---------------- K1: forward DFT along w (radix-4 decimation in time) ------
// block=(n,h), 128 thr. u-precompute then 64-term contraction per ky.
__global__ __launch_bounds__(128) void k1_fwd_w(const float* __restrict__ x) {
    extern __shared__ __align__(16) float us[];   // u0|u2|d02|d13, each [64][64]
    __shared__ __align__(16) float4 twp[256], twn[256];
    const int t = threadIdx.x;
    twp[t] = g_tw4p[t]; twp[t+128] = g_tw4p[t+128];
    twn[t] = g_tw4n[t]; twn[t+128] = g_tw4n[t+128];
    const int b = blockIdx.x, n = b >> 8, h = b & 255;
    const float* xb = x + (size_t)(n*RR + h)*RR*IND;
    float* u0s = us; float* u2s = us + 4096; float* d2s = us + 8192; float* d3s = us + 12288;
#pragma unroll
    for (int it = 0; it < 32; it++) {
        int idx = t + 128*it;                    // idx = w0*64 + i
        float a0 = xb[idx], a1 = xb[idx + 4096], a2 = xb[idx + 8192], a3 = xb[idx + 12288];
        float s02 = a0 + a2, d02 = a0 - a2, s13 = a1 + a3, d13 = a1 - a3;
        u0s[idx] = s02 + s13; u2s[idx] = s02 - s13; d2s[idx] = d02; d3s[idx] = d13;
    }
    __syncthreads();

    const int i0 = (t & 15) * 4, ky0 = (t >> 4) * 4;
    ull aR0[2]={0,0}, aI0[2]={0,0}, aR2[2]={0,0}, aI2[2]={0,0};
    ull aR1[2]={0,0}, bI1[2]={0,0}, aR3[2]={0,0}, aI3[2]={0,0};
    int p0 = 0, p1 = 0, p2 = 0, p3 = 0;
    for (int w0 = 0; w0 < 64; w0++) {
        const int off = w0*64 + i0;
        ulonglong2 U0 = *reinterpret_cast<const ulonglong2*>(&u0s[off]);
        ulonglong2 U2 = *reinterpret_cast<const ulonglong2*>(&u2s[off]);
        ulonglong2 D2 = *reinterpret_cast<const ulonglong2*>(&d2s[off]);
        ulonglong2 D3 = *reinterpret_cast<const ulonglong2*>(&d3s[off]);
        // k=0 (c=0): XR += c*u0 ; XI += -s*u0
        ulonglong2 tn4 = *reinterpret_cast<const ulonglong2*>(&twn[p0]);
        fma2(aR0[0], tn4.x, U0.x); fma2(aR0[1], tn4.x, U0.y);
        fma2(aI0[0], tn4.y, U0.x); fma2(aI0[1], tn4.y, U0.y);
        p0 = (p0 + ky0) & 255;
        // k=1 (c=1): u=(d02,-d13): XR += c*d02 - s*d13 ; -XI += c*d13 + s*d02
        ulonglong2 tp4 = *reinterpret_cast<const ulonglong2*>(&twp[p1]);
        tn4 = *reinterpret_cast<const ulonglong2*>(&twn[p1]);
        fma2(aR1[0], tp4.x, D2.x); fma2(aR1[1], tp4.x, D2.y);
        fma2(aR1[0], tn4.y, D3.x); fma2(aR1[1], tn4.y, D3.y);
        fma2(bI1[0], tp4.x, D3.x); fma2(bI1[1], tp4.x, D3.y);
        fma2(bI1[0], tp4.y, D2.x); fma2(bI1[1], tp4.y, D2.y);
        p1 = (p1 + ky0 + 1) & 255;
        // k=2 (c=2): like k=0 with u2
        tn4 = *reinterpret_cast<const ulonglong2*>(&twn[p2]);
        fma2(aR2[0], tn4.x, U2.x); fma2(aR2[1], tn4.x, U2.y);
        fma2(aI2[0], tn4.y, U2.x); fma2(aI2[1], tn4.y, U2.y);
        p2 = (p2 + ky0 + 2) & 255;
        // k=3 (c=3): u=(d02,+d13): XR += c*d02 + s*d13 ; XI += c*d13 - s*d02
        tp4 = *reinterpret_cast<const ulonglong2*>(&twp[p3]);
        tn4 = *reinterpret_cast<const ulonglong2*>(&twn[p3]);
        fma2(aR3[0], tp4.x, D2.x); fma2(aR3[1], tp4.x, D2.y);
        fma2(aR3[0], tp4.y, D3.x); fma2(aR3[1], tp4.y, D3.y);
        fma2(aI3[0], tp4.x, D3.x); fma2(aI3[1], tp4.x, D3.y);
        fma2(aI3[0], tn4.y, D2.x); fma2(aI3[1], tn4.y, D2.y);
        p3 = (p3 + ky0 + 3) & 255;
    }
    const float sc = 1.f/256.f;
    ull* Rs[4] = {aR0, aR1, aR2, aR3};
    ull* Is[4] = {aI0, bI1, aI2, aI3};
    const float isc[4] = {sc, -sc, sc, sc};
#pragma unroll
    for (int k = 0; k < 4; k++) {
        size_t o = (size_t)((n*MD + ky0 + k)*RR + h)*IND + i0;
        float2 a0 = unpk(Rs[k][0]), a1 = unpk(Rs[k][1]);
        *reinterpret_cast<float4*>(&g_XwR[o]) = make_float4(a0.x*sc, a0.y*sc, a1.x*sc, a1.y*sc);
        a0 = unpk(Is[k][0]); a1 = unpk(Is[k][1]);
        float f = isc[k];
        *reinterpret_cast<float4*>(&g_XwI[o]) = make_float4(a0.x*f, a0.y*f, a1.x*f, a1.y*f);
    }
}

// ---------------- K2: forward DFT along h (complex), kx in {0..31,224..255} -
__global__ __launch_bounds__(256) void k2_fwd_h() {
    __shared__ __align__(16) float sR[64*IND], sI[64*IND];
    __shared__ __align__(16) float4 tws[256];         // (c,c,s,s)
    const int t = threadIdx.x;
    tws[t] = g_tw4p[t];
    const int b = blockIdx.x, half = b & 1, ky = (b >> 1) & 31, n = b >> 6;
    const float* baseR = g_XwR + (size_t)(n*MD + ky)*RR*IND;
    const float* baseI = g_XwI + (size_t)(n*MD + ky)*RR*IND;
    const int i0 = (t & 15) * 4, kxl = (t >> 4) * 2;
    const int kap0 = half ? (224 + kxl) : kxl;
    ull aR[2][2], aI[2][2];
    aR[0][0]=aR[0][1]=aR[1][0]=aR[1][1]=0ull;
    aI[0][0]=aI[0][1]=aI[1][0]=aI[1][1]=0ull;
    int p0 = 0, p1 = 0;
    const ull NEG1 = splat2(-1.f);
    for (int hc = 0; hc < RR; hc += 64) {
        __syncthreads();
        const float4* pR = reinterpret_cast<const float4*>(baseR + hc*IND);
        const float4* pI = reinterpret_cast<const float4*>(baseI + hc*IND);
#pragma unroll
        for (int it = 0; it < 4; it++) {
            reinterpret_cast<float4*>(sR)[t + 256*it] = pR[t + 256*it];
            reinterpret_cast<float4*>(sI)[t + 256*it] = pI[t + 256*it];
        }
        __syncthreads();
        for (int hh = 0; hh < 64; hh++) {
            ulonglong2 Rp = *reinterpret_cast<const ulonglong2*>(&sR[hh*IND + i0]);
            ulonglong2 Ip = *reinterpret_cast<const ulonglong2*>(&sI[hh*IND + i0]);
            ull Rn0 = neg2(Rp.x, NEG1), Rn1 = neg2(Rp.y, NEG1);
            ulonglong2 t4 = *reinterpret_cast<const ulonglong2*>(&tws[p0]);
            fma2(aR[0][0], t4.x, Rp.x); fma2(aR[0][0], t4.y, Ip.x);
            fma2(aR[0][1], t4.x, Rp.y); fma2(aR[0][1], t4.y, Ip.y);
            fma2(aI[0][0], t4.x, Ip.x); fma2(aI[0][0], t4.y, Rn0);
            fma2(aI[0][1], t4.x, Ip.y); fma2(aI[0][1], t4.y, Rn1);
            p0 = (p0 + kap0) & 255;
            t4 = *reinterpret_cast<const ulonglong2*>(&tws[p1]);
            fma2(aR[1][0], t4.x, Rp.x); fma2(aR[1][0], t4.y, Ip.x);
            fma2(aR[1][1], t4.x, Rp.y); fma2(aR[1][1], t4.y, Ip.y);
            fma2(aI[1][0], t4.x, Ip.x); fma2(aI[1][0], t4.y, Rn0);
            fma2(aI[1][1], t4.x, Ip.y); fma2(aI[1][1], t4.y, Rn1);
            p1 = (p1 + kap0 + 1) & 255;
        }
    }
#pragma unroll
    for (int kk = 0; kk < 2; kk++) {
        int kxs = half*32 + kxl + kk;
        size_t o = (size_t)((ky*KXN + kxs)*NB + n)*IND + i0;
        float2 a0 = unpk(aR[kk][0]), a1 = unpk(aR[kk][1]);
        *reinterpret_cast<float4*>(&g_XmR[o]) = make_float4(a0.x, a0.y, a1.x, a1.y);
        a0 = unpk(aI[kk][0]); a1 = unpk(aI[kk][1]);
        *reinterpret_cast<float4*>(&g_XmI[o]) = make_float4(a0.x, a0.y, a1.x, a1.y);
    }
}

// ---------------- K3: per-mode complex channel mix (8x64x64) ----------------
__global__ __launch_bounds__(256) void k3_mix(const float* __restrict__ w0,
                                              const float* __restrict__ w1) {
    __shared__ float XsR[NB*IND], XsI[NB*IND];
    const int t = threadIdx.x, b = blockIdx.x;
    const int kx = b >> 5, ky = b & 31;
    size_t xb = (size_t)(ky*KXN + kx)*NB*IND;
    XsR[t] = g_XmR[xb + t]; XsR[t + 256] = g_XmR[xb + t + 256];
    XsI[t] = g_XmI[xb + t]; XsI[t + 256] = g_XmI[xb + t + 256];
    __syncthreads();
    const float2* wp = reinterpret_cast<const float2*>(
        (kx < MD) ? (w0 + (size_t)(kx*MD + ky)*IND*OUTD*2)
                  : (w1 + (size_t)((kx - MD)*MD + ky)*IND*OUTD*2));
    const int o = t & 63, n0 = t >> 6;
    float r0 = 0.f, i0 = 0.f, r1 = 0.f, i1 = 0.f;
#pragma unroll 8
    for (int i = 0; i < IND; i++) {
        float2 wv = wp[i*OUTD + o];
        float xr = XsR[n0*IND + i], xi = XsI[n0*IND + i];
        r0 = fmaf(xr, wv.x, fmaf(-xi, wv.y, r0));
        i0 = fmaf(xr, wv.y, fmaf( xi, wv.x, i0));
        xr = XsR[(n0+4)*IND + i]; xi = XsI[(n0+4)*IND + i];
        r1 = fmaf(xr, wv.x, fmaf(-xi, wv.y, r1));
        i1 = fmaf(xr, wv.y, fmaf( xi, wv.x, i1));
    }
    size_t g0 = (size_t)((n0*MD + ky)*KXN + kx)*OUTD + o;
    g_OmR[g0] = r0; g_OmI[g0] = i0;
    size_t g1 = (size_t)(((n0+4)*MD + ky)*KXN + kx)*OUTD + o;
    g_OmR[g1] = r1; g_OmI[g1] = i1;
}

// ---------------- K4: inverse DFT along h -----------------------------------
__global__ __launch_bounds__(256) void k4_inv_h() {
    __shared__ __align__(16) float sR[KXN*OUTD], sI[KXN*OUTD];
    __shared__ __align__(16) float4 tws[256];         // (c,c,s,s)
    const int t = threadIdx.x;
    tws[t] = g_tw4p[t];
    const int b = blockIdx.x, grp = b & 3, ky = (b >> 2) & 31, n = b >> 7;
    const float4* pR = reinterpret_cast<const float4*>(g_OmR + (size_t)(n*MD + ky)*KXN*OUTD);
    const float4* pI = reinterpret_cast<const float4*>(g_OmI + (size_t)(n*MD + ky)*KXN*OUTD);
#pragma unroll
    for (int it = 0; it < 4; it++) {
        reinterpret_cast<float4*>(sR)[t + 256*it] = pR[t + 256*it];
        reinterpret_cast<float4*>(sI)[t + 256*it] = pI[t + 256*it];
    }
    __syncthreads();
    const int o0 = (t & 15) * 4, hG = t >> 4;
    int hj[4];
#pragma unroll
    for (int j = 0; j < 4; j++) hj[j] = grp*64 + hG*4 + j;
    ull aR[4][2], aI[4][2];
#pragma unroll
    for (int j = 0; j < 4; j++) { aR[j][0]=aR[j][1]=aI[j][0]=aI[j][1]=0ull; }
    const ull NEG1 = splat2(-1.f);
#pragma unroll 1
    for (int kh = 0; kh < 2; kh++) {
        const int kapb = kh ? 224 : 0;
        int p[4];
#pragma unroll
        for (int j = 0; j < 4; j++) p[j] = (kapb * hj[j]) & 255;
        for (int kk = 0; kk < 32; kk++) {
            const int kx = kh*32 + kk;
            ulonglong2 Rp = *reinterpret_cast<const ulonglong2*>(&sR[kx*OUTD + o0]);
            ulonglong2 Ip = *reinterpret_cast<const ulonglong2*>(&sI[kx*OUTD + o0]);
            ull In0 = neg2(Ip.x, NEG1), In1 = neg2(Ip.y, NEG1);
#pragma unroll
            for (int j = 0; j < 4; j++) {
                ulonglong2 t4 = *reinterpret_cast<const ulonglong2*>(&tws[p[j]]);
                fma2(aR[j][0], t4.x, Rp.x); fma2(aR[j][0], t4.y, In0);
                fma2(aR[j][1], t4.x, Rp.y); fma2(aR[j][1], t4.y, In1);
                fma2(aI[j][0], t4.x, Ip.x); fma2(aI[j][0], t4.y, Rp.x);
                fma2(aI[j][1], t4.x, Ip.y); fma2(aI[j][1], t4.y, Rp.y);
                p[j] = (p[j] + hj[j]) & 255;
            }
        }
    }
    const float fac = (ky == 0 ? 1.f : 2.f) * (1.f/256.f);
#pragma unroll
    for (int j = 0; j < 4; j++) {
        size_t o = (size_t)((n*RR + hj[j])*MD + ky)*OUTD + o0;
        float2 a0 = unpk(aR[j][0]), a1 = unpk(aR[j][1]);
        *reinterpret_cast<float4*>(&g_Y1R[o]) = make_float4(a0.x*fac, a0.y*fac, a1.x*fac, a1.y*fac);
        a0 = unpk(aI[j][0]); a1 = unpk(aI[j][1]);
        *reinterpret_cast<float4*>(&g_Y1I[o]) = make_float4(a0.x*fac, a0.y*fac, a1.x*fac, a1.y*fac);
    }
}

// ---------------- K5: radix-4 inverse w synthesis + residual + SiLU ---------
// block=(n,h), 256 thr: w0 = t>>2 in [0,64), ogrp = t&3 (8 o), two o-halves.
#define XPAD 68
__global__ __launch_bounds__(256) void k5_inv_w(const float* __restrict__ x,
                                                const float* __restrict__ res_w,
                                                const float* __restrict__ res_b,
                                                float* __restrict__ out) {
    extern __shared__ __align__(16) float xs[];       // [256][XPAD]
    __shared__ __align__(16) float YsR[MD*OUTD], YsI[MD*OUTD];
    __shared__ __align__(16) float rws[IND*OUTD];
    __shared__ __align__(16) float4 twp[256], twn[256];
    __shared__ __align__(16) float rbs[64];
    const int t = threadIdx.x, b = blockIdx.x, n = b >> 8, h = b & 255;
    twp[t] = g_tw4p[t];
    twn[t] = g_tw4n[t];
    const float4* xp = reinterpret_cast<const float4*>(x + (size_t)(n*RR + h)*RR*IND);
#pragma unroll
    for (int it = 0; it < 16; it++) {
        int j = t + 256*it;
        float4 v = xp[j];
        int w = j >> 4, c = j & 15;
        *reinterpret_cast<float4*>(&xs[w*XPAD + c*4]) = v;
    }
    const float4* yR4 = reinterpret_cast<const float4*>(g_Y1R + (size_t)(n*RR + h)*MD*OUTD);
    const float4* yI4 = reinterpret_cast<const float4*>(g_Y1I + (size_t)(n*RR + h)*MD*OUTD);
#pragma unroll
    for (int it = 0; it < 2; it++) {
        reinterpret_cast<float4*>(YsR)[t + 256*it] = yR4[t + 256*it];
        reinterpret_cast<float4*>(YsI)[t + 256*it] = yI4[t + 256*it];
    }
#pragma unroll
    for (int it = 0; it < 4; it++)
        reinterpret_cast<float4*>(rws)[t + 256*it] =
            reinterpret_cast<const float4*>(res_w)[t + 256*it];
    if (t < 64) rbs[t] = res_b[t];
    __syncthreads();

    const int ogrp = t & 3, w0 = t >> 2;
    const ull NEG1 = splat2(-1.f);
#pragma unroll 1
    for (int oh = 0; oh < 2; oh++) {
        const int o0 = oh*32 + ogrp*8;
        // ---- spectral class accumulation ----
        ull C0R[4], C2R[4], C1R[4], C1I[4], C3R[4], C3I[4];
#pragma unroll
        for (int j = 0; j < 4; j++) { C0R[j]=C2R[j]=C1R[j]=C1I[j]=C3R[j]=C3I[j]=0ull; }
        int p = 0;
#pragma unroll
        for (int kb = 0; kb < 8; kb++) {
            // c = 0
            {
                const int ky = 4*kb;
                ulonglong2 yr0 = *reinterpret_cast<const ulonglong2*>(&YsR[ky*OUTD + o0]);
                ulonglong2 yr1 = *reinterpret_cast<const ulonglong2*>(&YsR[ky*OUTD + o0 + 4]);
                ulonglong2 yi0 = *reinterpret_cast<const ulonglong2*>(&YsI[ky*OUTD + o0]);
                ulonglong2 yi1 = *reinterpret_cast<const ulonglong2*>(&YsI[ky*OUTD + o0 + 4]);
                ulonglong2 tn4 = *reinterpret_cast<const ulonglong2*>(&twn[p]);
                fma2(C0R[0], tn4.x, yr0.x); fma2(C0R[0], tn4.y, yi0.x);
                fma2(C0R[1], tn4.x, yr0.y); fma2(C0R[1], tn4.y, yi0.y);
                fma2(C0R[2], tn4.x, yr1.x); fma2(C0R[2], tn4.y, yi1.x);
                fma2(C0R[3], tn4.x, yr1.y); fma2(C0R[3], tn4.y, yi1.y);
                p = (p + w0) & 255;
            }
            // c = 1
            {
                const int ky = 4*kb + 1;
                ulonglong2 yr0 = *reinterpret_cast<const ulonglong2*>(&YsR[ky*OUTD + o0]);
                ulonglong2 yr1 = *reinterpret_cast<const ulonglong2*>(&YsR[ky*OUTD + o0 + 4]);
                ulonglong2 yi0 = *reinterpret_cast<const ulonglong2*>(&YsI[ky*OUTD + o0]);
                ulonglong2 yi1 = *reinterpret_cast<const ulonglong2*>(&YsI[ky*OUTD + o0 + 4]);
                ulonglong2 tn4 = *reinterpret_cast<const ulonglong2*>(&twn[p]);
                ulonglong2 tp4 = *reinterpret_cast<const ulonglong2*>(&twp[p]);
                fma2(C1R[0], tn4.x, yr0.x); fma2(C1R[0], tn4.y, yi0.x);
                fma2(C1R[1], tn4.x, yr0.y); fma2(C1R[1], tn4.y, yi0.y);
                fma2(C1R[2], tn4.x, yr1.x); fma2(C1R[2], tn4.y, yi1.x);
                fma2(C1R[3], tn4.x, yr1.y); fma2(C1R[3], tn4.y, yi1.y);
                fma2(C1I[0], tp4.x, yi0.x); fma2(C1I[0], tp4.y, yr0.x);
                fma2(C1I[1], tp4.x, yi0.y); fma2(C1I[1], tp4.y, yr0.y);
                fma2(C1I[2], tp4.x, yi1.x); fma2(C1I[2], tp4.y, yr1.x);
                fma2(C1I[3], tp4.x, yi1.y); fma2(C1I[3], tp4.y, yr1.y);
                p = (p + w0) & 255;
            }
            // c = 2
            {
                const int ky = 4*kb + 2;
                ulonglong2 yr0 = *reinterpret_cast<const ulonglong2*>(&YsR[ky*OUTD + o0]);
                ulonglong2 yr1 = *reinterpret_cast<const ulonglong2*>(&YsR[ky*OUTD + o0 + 4]);
                ulonglong2 yi0 = *reinterpret_cast<const ulonglong2*>(&YsI[ky*OUTD + o0]);
                ulonglong2 yi1 = *reinterpret_cast<const ulonglong2*>(&YsI[ky*OUTD + o0 + 4]);
                ulonglong2 tn4 = *reinterpret_cast<const ulonglong2*>(&twn[p]);
                fma2(C2R[0], tn4.x, yr0.x); fma2(C2R[0], tn4.y, yi0.x);
                fma2(C2R[1], tn4.x, yr0.y); fma2(C2R[1], tn4.y, yi0.y);
                fma2(C2R[2], tn4.x, yr1.x); fma2(C2R[2], tn4.y, yi1.x);
                fma2(C2R[3], tn4.x, yr1.y); fma2(C2R[3], tn4.y, yi1.y);
                p = (p + w0) & 255;
            }
            // c = 3
            {
                const int ky = 4*kb + 3;
                ulonglong2 yr0 = *reinterpret_cast<const ulonglong2*>(&YsR[ky*OUTD + o0]);
                ulonglong2 yr1 = *reinterpret_cast<const ulonglong2*>(&YsR[ky*OUTD + o0 + 4]);
                ulonglong2 yi0 = *reinterpret_cast<const ulonglong2*>(&YsI[ky*OUTD + o0]);
                ulonglong2 yi1 = *reinterpret_cast<const ulonglong2*>(&YsI[ky*OUTD + o0 + 4]);
                ulonglong2 tn4 = *reinterpret_cast<const ulonglong2*>(&twn[p]);
                ulonglong2 tp4 = *reinterpret_cast<const ulonglong2*>(&twp[p]);
                fma2(C3R[0], tn4.x, yr0.x); fma2(C3R[0], tn4.y, yi0.x);
                fma2(C3R[1], tn4.x, yr0.y); fma2(C3R[1], tn4.y, yi0.y);
                fma2(C3R[2], tn4.x, yr1.x); fma2(C3R[2], tn4.y, yi1.x);
                fma2(C3R[3], tn4.x, yr1.y); fma2(C3R[3], tn4.y, yi1.y);
                fma2(C3I[0], tp4.x, yi0.x); fma2(C3I[0], tp4.y, yr0.x);
                fma2(C3I[1], tp4.x, yi0.y); fma2(C3I[1], tp4.y, yr0.y);
                fma2(C3I[2], tp4.x, yi1.x); fma2(C3I[2], tp4.y, yr1.x);
                fma2(C3I[3], tp4.x, yi1.y); fma2(C3I[3], tp4.y, yr1.y);
                p = (p + w0) & 255;
            }
        }
        // ---- combine classes into 4 output rows + bias ----
        ull y[4][4];
        {
            ulonglong2 b01 = *reinterpret_cast<const ulonglong2*>(&rbs[o0]);
            ulonglong2 b23 = *reinterpret_cast<const ulonglong2*>(&rbs[o0 + 4]);
            ull bias[4] = {b01.x, b01.y, b23.x, b23.y};
#pragma unroll
            for (int j = 0; j < 4; j++) {
                ull e  = add2(C0R[j], C2R[j]);
                ull f  = sub2(C0R[j], C2R[j], NEG1);
                ull g  = add2(C1R[j], C3R[j]);
                ull hh = sub2(C3I[j], C1I[j], NEG1);
                y[0][j] = add2(add2(e, g),  bias[j]);
                y[2][j] = add2(sub2(e, g,  NEG1), bias[j]);
                y[1][j] = add2(add2(f, hh), bias[j]);
                y[3][j] = add2(sub2(f, hh, NEG1), bias[j]);
            }
        }
        // ---- residual GEMM into y ----
        for (int i = 0; i < IND; i++) {
            ulonglong2 r01 = *reinterpret_cast<const ulonglong2*>(&rws[i*OUTD + o0]);
            ulonglong2 r23 = *reinterpret_cast<const ulonglong2*>(&rws[i*OUTD + o0 + 4]);
#pragma unroll
            for (int q = 0; q < 4; q++) {
                ull sx = splat2(xs[(w0 + 64*q)*XPAD + i]);
                fma2(y[q][0], sx, r01.x); fma2(y[q][1], sx, r01.y);
                fma2(y[q][2], sx, r23.x); fma2(y[q][3], sx, r23.y);
            }
        }
        // ---- SiLU + store ----
#pragma unroll
        for (int q = 0; q < 4; q++) {
            float4 v4[2];
#pragma unroll
            for (int c = 0; c < 4; c++) {
                float2 v = unpk(y[q][c]);
                v.x = v.x / (1.f + __expf(-v.x));
                v.y = v.y / (1.f + __expf(-v.y));
                reinterpret_cast<float2*>(v4)[c] = v;
            }
            size_t o = (size_t)((n*RR + h)*RR + (w0 + 64*q))*OUTD + o0;
            *reinterpret_cast<float4*>(&out[o])     = v4[0];
            *reinterpret_cast<float4*>(&out[o + 4]) = v4[1];
        }
    }
}

// ---------------- launch ----------------------------------------------------
extern "C" void kernel_launch(void* const* d_in, const int* in_sizes, int n_in,
                              void* d_out, int out_size) {
    const float* x   = (const float*)d_in[0];
    const float* w0  = (const float*)d_in[1];
    const float* w1  = (const float*)d_in[2];
    const float* rsw = (const float*)d_in[3];
    const float* rsb = (const float*)d_in[4];
    float* out = (float*)d_out;

    cudaFuncSetAttribute(k1_fwd_w, cudaFuncAttributeMaxDynamicSharedMemorySize, 65536);
    cudaFuncSetAttribute(k5_inv_w, cudaFuncAttributeMaxDynamicSharedMemorySize, RR*XPAD*4);

    k_init_tw<<<1, 256>>>();
    k1_fwd_w<<<NB*RR, 128, 65536>>>(x);
    k2_fwd_h<<<NB*MD*2, 256>>>();
    k3_mix<<<KXN*MD, 256>>>(w0, w1);
    k4_inv_h<<<NB*MD*4, 256>>>();
    k5_inv_w<<<NB*RR, 256, RR*XPAD*4>>>(x, rsw, rsb, out);
}

// round 6
// speedup vs baseline: 2.2369x; 1.1086x over previous
#include <cuda_runtime.h>

#define NB   8
#define RR   256
#define IND  64
#define OUTD 64
#define MD   32
#define KXN  64

typedef unsigned long long ull;

// ---------------- scratch (device globals; no allocations allowed) ----------
__device__ float g_XwR[NB*MD*RR*IND];     // [n][ky][h][i]  forward w-DFT (re)
__device__ float g_XwI[NB*MD*RR*IND];
__device__ float g_XmR[NB*MD*KXN*IND];    // [ky][kx][n][i] forward modes
__device__ float g_XmI[NB*MD*KXN*IND];
__device__ float g_OmR[NB*MD*KXN*OUTD];   // [n][ky][kx][o] mixed modes
__device__ float g_OmI[NB*MD*KXN*OUTD];
__device__ float g_Y1R[NB*RR*MD*OUTD];    // [n][h][ky][o]  after inverse h-DFT
__device__ float g_Y1I[NB*RR*MD*OUTD];
__device__ float4 g_tw4p[256];            // (c, c,  s,  s)
__device__ float4 g_tw4n[256];            // (c, c, -s, -s)

// ---------------- packed f32x2 helpers --------------------------------------
__device__ __forceinline__ void fma2(ull &d, ull a, ull b) {
    asm("fma.rn.f32x2 %0, %1, %2, %0;" : "+l"(d) : "l"(a), "l"(b));
}
__device__ __forceinline__ ull splat2(float x) {
    ull r; asm("mov.b64 %0, {%1, %1};" : "=l"(r) : "f"(x)); return r;
}
__device__ __forceinline__ ull neg2(ull a, ull negone) {
    ull r; asm("mul.rn.f32x2 %0, %1, %2;" : "=l"(r) : "l"(a), "l"(negone)); return r;
}
__device__ __forceinline__ ull mul2(ull a, ull b) {
    ull r; asm("mul.rn.f32x2 %0, %1, %2;" : "=l"(r) : "l"(a), "l"(b)); return r;
}
__device__ __forceinline__ ull add2(ull a, ull b) {
    ull r; asm("add.rn.f32x2 %0, %1, %2;" : "=l"(r) : "l"(a), "l"(b)); return r;
}
__device__ __forceinline__ ull sub2(ull a, ull b, ull negone) {   // a - b
    ull r; asm("fma.rn.f32x2 %0, %1, %2, %3;" : "=l"(r) : "l"(b), "l"(negone), "l"(a)); return r;
}
__device__ __forceinline__ float2 unpk(ull v) {
    float2 r; asm("mov.b64 {%0, %1}, %2;" : "=f"(r.x), "=f"(r.y) : "l"(v)); return r;
}

__global__ void k_init_tw() {
    int k = threadIdx.x;
    double a = 6.283185307179586476925286766559 * (double)k / 256.0;
    float c = (float)cos(a), s = (float)sin(a);
    g_tw4p[k] = make_float4(c, c,  s,  s);
    g_tw4n[k] = make_float4(c, c, -s, -s);
}

// ---------------- K1: forward DFT along w (radix-4 decimation in time) ------
__global__ __launch_bounds__(128) void k1_fwd_w(const float* __restrict__ x) {
    extern __shared__ __align__(16) float us[];   // u0|u2|d02|d13, each [64][64]
    __shared__ __align__(16) float4 twp[256], twn[256];
    const int t = threadIdx.x;
    twp[t] = g_tw4p[t]; twp[t+128] = g_tw4p[t+128];
    twn[t] = g_tw4n[t]; twn[t+128] = g_tw4n[t+128];
    const int b = blockIdx.x, n = b >> 8, h = b & 255;
    const float* xb = x + (size_t)(n*RR + h)*RR*IND;
    float* u0s = us; float* u2s = us + 4096; float* d2s = us + 8192; float* d3s = us + 12288;
#pragma unroll
    for (int it = 0; it < 32; it++) {
        int idx = t + 128*it;                    // idx = w0*64 + i
        float a0 = xb[idx], a1 = xb[idx + 4096], a2 = xb[idx + 8192], a3 = xb[idx + 12288];
        float s02 = a0 + a2, d02 = a0 - a2, s13 = a1 + a3, d13 = a1 - a3;
        u0s[idx] = s02 + s13; u2s[idx] = s02 - s13; d2s[idx] = d02; d3s[idx] = d13;
    }
    __syncthreads();

    const int i0 = (t & 15) * 4, ky0 = (t >> 4) * 4;
    ull aR0[2]={0,0}, aI0[2]={0,0}, aR2[2]={0,0}, aI2[2]={0,0};
    ull aR1[2]={0,0}, bI1[2]={0,0}, aR3[2]={0,0}, aI3[2]={0,0};
    int p0 = 0, p1 = 0, p2 = 0, p3 = 0;
    for (int w0 = 0; w0 < 64; w0++) {
        const int off = w0*64 + i0;
        ulonglong2 U0 = *reinterpret_cast<const ulonglong2*>(&u0s[off]);
        ulonglong2 U2 = *reinterpret_cast<const ulonglong2*>(&u2s[off]);
        ulonglong2 D2 = *reinterpret_cast<const ulonglong2*>(&d2s[off]);
        ulonglong2 D3 = *reinterpret_cast<const ulonglong2*>(&d3s[off]);
        ulonglong2 tn4 = *reinterpret_cast<const ulonglong2*>(&twn[p0]);
        fma2(aR0[0], tn4.x, U0.x); fma2(aR0[1], tn4.x, U0.y);
        fma2(aI0[0], tn4.y, U0.x); fma2(aI0[1], tn4.y, U0.y);
        p0 = (p0 + ky0) & 255;
        ulonglong2 tp4 = *reinterpret_cast<const ulonglong2*>(&twp[p1]);
        tn4 = *reinterpret_cast<const ulonglong2*>(&twn[p1]);
        fma2(aR1[0], tp4.x, D2.x); fma2(aR1[1], tp4.x, D2.y);
        fma2(aR1[0], tn4.y, D3.x); fma2(aR1[1], tn4.y, D3.y);
        fma2(bI1[0], tp4.x, D3.x); fma2(bI1[1], tp4.x, D3.y);
        fma2(bI1[0], tp4.y, D2.x); fma2(bI1[1], tp4.y, D2.y);
        p1 = (p1 + ky0 + 1) & 255;
        tn4 = *reinterpret_cast<const ulonglong2*>(&twn[p2]);
        fma2(aR2[0], tn4.x, U2.x); fma2(aR2[1], tn4.x, U2.y);
        fma2(aI2[0], tn4.y, U2.x); fma2(aI2[1], tn4.y, U2.y);
        p2 = (p2 + ky0 + 2) & 255;
        tp4 = *reinterpret_cast<const ulonglong2*>(&twp[p3]);
        tn4 = *reinterpret_cast<const ulonglong2*>(&twn[p3]);
        fma2(aR3[0], tp4.x, D2.x); fma2(aR3[1], tp4.x, D2.y);
        fma2(aR3[0], tp4.y, D3.x); fma2(aR3[1], tp4.y, D3.y);
        fma2(aI3[0], tp4.x, D3.x); fma2(aI3[1], tp4.x, D3.y);
        fma2(aI3[0], tn4.y, D2.x); fma2(aI3[1], tn4.y, D2.y);
        p3 = (p3 + ky0 + 3) & 255;
    }
    const float sc = 1.f/256.f;
    ull* Rs[4] = {aR0, aR1, aR2, aR3};
    ull* Is[4] = {aI0, bI1, aI2, aI3};
    const float isc[4] = {sc, -sc, sc, sc};
#pragma unroll
    for (int k = 0; k < 4; k++) {
        size_t o = (size_t)((n*MD + ky0 + k)*RR + h)*IND + i0;
        float2 a0 = unpk(Rs[k][0]), a1 = unpk(Rs[k][1]);
        *reinterpret_cast<float4*>(&g_XwR[o]) = make_float4(a0.x*sc, a0.y*sc, a1.x*sc, a1.y*sc);
        a0 = unpk(Is[k][0]); a1 = unpk(Is[k][1]);
        float f = isc[k];
        *reinterpret_cast<float4*>(&g_XwI[o]) = make_float4(a0.x*f, a0.y*f, a1.x*f, a1.y*f);
    }
}

// ---------------- K2: forward h-DFT, radix-4 decimation in time -------------
// block=(n,ky,half). Loader butterflies 4 q-rows into class planes V_c, then
// each thread contracts 64 h0 terms for 2 kappa of one class.
__global__ __launch_bounds__(256) void k2_fwd_h() {
    __shared__ __align__(16) float Vs[8*16*64];       // [class*2+ri][16 h0][64 i]
    __shared__ __align__(16) float4 twp[256], twn[256];
    const int t = threadIdx.x;
    twp[t] = g_tw4p[t]; twn[t] = g_tw4n[t];
    const int b = blockIdx.x, half = b & 1, ky = (b >> 1) & 31, n = b >> 6;
    const float* baseR = g_XwR + (size_t)(n*MD + ky)*RR*IND;
    const float* baseI = g_XwI + (size_t)(n*MD + ky)*RR*IND;
    const int i0 = (t & 15) * 4;
    const int g = t >> 4, c = g & 3, mseg = g >> 2;
    const int kxl0 = 8*mseg + c;                       // slots of class c
    const int kap0 = half ? (224 + kxl0) : kxl0;
    const int kap1 = kap0 + 4;
    const int h0ld = t >> 4, iq = (t & 15) * 4;        // loader roles
    const ull NEG1 = splat2(-1.f);
    ull aR[2][2] = {{0,0},{0,0}}, aI[2][2] = {{0,0},{0,0}};
    int p0 = 0, p1 = 0;

    for (int hc = 0; hc < 64; hc += 16) {
        __syncthreads();
        {   // butterfly loader: one thread per (h0, i-quad)
            const float* pR = baseR + (hc + h0ld)*IND + iq;
            const float* pI = baseI + (hc + h0ld)*IND + iq;
            ulonglong2 R0 = *reinterpret_cast<const ulonglong2*>(pR);
            ulonglong2 R1 = *reinterpret_cast<const ulonglong2*>(pR + 64*IND);
            ulonglong2 R2 = *reinterpret_cast<const ulonglong2*>(pR + 128*IND);
            ulonglong2 R3 = *reinterpret_cast<const ulonglong2*>(pR + 192*IND);
            ulonglong2 I0 = *reinterpret_cast<const ulonglong2*>(pI);
            ulonglong2 I1 = *reinterpret_cast<const ulonglong2*>(pI + 64*IND);
            ulonglong2 I2 = *reinterpret_cast<const ulonglong2*>(pI + 128*IND);
            ulonglong2 I3 = *reinterpret_cast<const ulonglong2*>(pI + 192*IND);
            ull sRx = add2(R0.x, R2.x), sRy = add2(R0.y, R2.y);
            ull dRx = sub2(R0.x, R2.x, NEG1), dRy = sub2(R0.y, R2.y, NEG1);
            ull uRx = add2(R1.x, R3.x), uRy = add2(R1.y, R3.y);
            ull eRx = sub2(R1.x, R3.x, NEG1), eRy = sub2(R1.y, R3.y, NEG1);
            ull sIx = add2(I0.x, I2.x), sIy = add2(I0.y, I2.y);
            ull dIx = sub2(I0.x, I2.x, NEG1), dIy = sub2(I0.y, I2.y, NEG1);
            ull uIx = add2(I1.x, I3.x), uIy = add2(I1.y, I3.y);
            ull eIx = sub2(I1.x, I3.x, NEG1), eIy = sub2(I1.y, I3.y, NEG1);
            const int rb = h0ld*64 + iq;
            ulonglong2* vp;
            vp = reinterpret_cast<ulonglong2*>(&Vs[0*1024 + rb]);   // V0R
            *vp = make_ulonglong2(add2(sRx, uRx), add2(sRy, uRy));
            vp = reinterpret_cast<ulonglong2*>(&Vs[1*1024 + rb]);   // V0I
            *vp = make_ulonglong2(add2(sIx, uIx), add2(sIy, uIy));
            vp = reinterpret_cast<ulonglong2*>(&Vs[2*1024 + rb]);   // V1R = dR + eI
            *vp = make_ulonglong2(add2(dRx, eIx), add2(dRy, eIy));
            vp = reinterpret_cast<ulonglong2*>(&Vs[3*1024 + rb]);   // V1I = dI - eR
            *vp = make_ulonglong2(sub2(dIx, eRx, NEG1), sub2(dIy, eRy, NEG1));
            vp = reinterpret_cast<ulonglong2*>(&Vs[4*1024 + rb]);   // V2R
            *vp = make_ulonglong2(sub2(sRx, uRx, NEG1), sub2(sRy, uRy, NEG1));
            vp = reinterpret_cast<ulonglong2*>(&Vs[5*1024 + rb]);   // V2I
            *vp = make_ulonglong2(sub2(sIx, uIx, NEG1), sub2(sIy, uIy, NEG1));
            vp = reinterpret_cast<ulonglong2*>(&Vs[6*1024 + rb]);   // V3R = dR - eI
            *vp = make_ulonglong2(sub2(dRx, eIx, NEG1), sub2(dRy, eIy, NEG1));
            vp = reinterpret_cast<ulonglong2*>(&Vs[7*1024 + rb]);   // V3I = dI + eR
            *vp = make_ulonglong2(add2(dIx, eRx), add2(dIy, eRy));
        }
        __syncthreads();
        const float* VRb = &Vs[(c*2 + 0)*1024];
        const float* VIb = &Vs[(c*2 + 1)*1024];
        for (int h0l = 0; h0l < 16; h0l++) {
            ulonglong2 VR = *reinterpret_cast<const ulonglong2*>(&VRb[h0l*64 + i0]);
            ulonglong2 VI = *reinterpret_cast<const ulonglong2*>(&VIb[h0l*64 + i0]);
            // e^{-i th}: R' += c*VR + s*VI ; I' += c*VI - s*VR
            ulonglong2 tp4 = *reinterpret_cast<const ulonglong2*>(&twp[p0]);
            ulonglong2 tn4 = *reinterpret_cast<const ulonglong2*>(&twn[p0]);
            fma2(aR[0][0], tp4.x, VR.x); fma2(aR[0][0], tp4.y, VI.x);
            fma2(aR[0][1], tp4.x, VR.y); fma2(aR[0][1], tp4.y, VI.y);
            fma2(aI[0][0], tp4.x, VI.x); fma2(aI[0][0], tn4.y, VR.x);
            fma2(aI[0][1], tp4.x, VI.y); fma2(aI[0][1], tn4.y, VR.y);
            p0 = (p0 + kap0) & 255;
            tp4 = *reinterpret_cast<const ulonglong2*>(&twp[p1]);
            tn4 = *reinterpret_cast<const ulonglong2*>(&twn[p1]);
            fma2(aR[1][0], tp4.x, VR.x); fma2(aR[1][0], tp4.y, VI.x);
            fma2(aR[1][1], tp4.x, VR.y); fma2(aR[1][1], tp4.y, VI.y);
            fma2(aI[1][0], tp4.x, VI.x); fma2(aI[1][0], tn4.y, VR.x);
            fma2(aI[1][1], tp4.x, VI.y); fma2(aI[1][1], tn4.y, VR.y);
            p1 = (p1 + kap1) & 255;
        }
    }
#pragma unroll
    for (int j = 0; j < 2; j++) {
        int kxs = half*32 + kxl0 + 4*j;
        size_t o = (size_t)((ky*KXN + kxs)*NB + n)*IND + i0;
        float2 a0 = unpk(aR[j][0]), a1 = unpk(aR[j][1]);
        *reinterpret_cast<float4*>(&g_XmR[o]) = make_float4(a0.x, a0.y, a1.x, a1.y);
        a0 = unpk(aI[j][0]); a1 = unpk(aI[j][1]);
        *reinterpret_cast<float4*>(&g_XmI[o]) = make_float4(a0.x, a0.y, a1.x, a1.y);
    }
}

// ---------------- K3: per-mode complex channel mix (8x64x64) ----------------
__global__ __launch_bounds__(256) void k3_mix(const float* __restrict__ w0,
                                              const float* __restrict__ w1) {
    __shared__ float XsR[NB*IND], XsI[NB*IND];
    const int t = threadIdx.x, b = blockIdx.x;
    const int kx = b >> 5, ky = b & 31;
    size_t xb = (size_t)(ky*KXN + kx)*NB*IND;
    XsR[t] = g_XmR[xb + t]; XsR[t + 256] = g_XmR[xb + t + 256];
    XsI[t] = g_XmI[xb + t]; XsI[t + 256] = g_XmI[xb + t + 256];
    __syncthreads();
    const float2* wp = reinterpret_cast<const float2*>(
        (kx < MD) ? (w0 + (size_t)(kx*MD + ky)*IND*OUTD*2)
                  : (w1 + (size_t)((kx - MD)*MD + ky)*IND*OUTD*2));
    const int o = t & 63, n0 = t >> 6;
    float r0 = 0.f, i0 = 0.f, r1 = 0.f, i1 = 0.f;
#pragma unroll 8
    for (int i = 0; i < IND; i++) {
        float2 wv = wp[i*OUTD + o];
        float xr = XsR[n0*IND + i], xi = XsI[n0*IND + i];
        r0 = fmaf(xr, wv.x, fmaf(-xi, wv.y, r0));
        i0 = fmaf(xr, wv.y, fmaf( xi, wv.x, i0));
        xr = XsR[(n0+4)*IND + i]; xi = XsI[(n0+4)*IND + i];
        r1 = fmaf(xr, wv.x, fmaf(-xi, wv.y, r1));
        i1 = fmaf(xr, wv.y, fmaf( xi, wv.x, i1));
    }
    size_t g0 = (size_t)((n0*MD + ky)*KXN + kx)*OUTD + o;
    g_OmR[g0] = r0; g_OmI[g0] = i0;
    size_t g1 = (size_t)(((n0+4)*MD + ky)*KXN + kx)*OUTD + o;
    g_OmR[g1] = r1; g_OmI[g1] = i1;
}

// ---------------- K4: inverse h-DFT, radix-4 on output ----------------------
// block=(n,ky,grp of 32 h0), 256 thr: o0=(t&7)*8, h0=grp*32 + (t>>3).
// C_c = sum_{kappa===c} Om * e^{+2pi i kappa h0/256}; Y[h0+64q] = sum_c i^{cq} C_c
#define K4STEP(CR, CI) { \
    ulonglong2 R0 = *reinterpret_cast<const ulonglong2*>(&sR[kxo]); \
    ulonglong2 R1 = *reinterpret_cast<const ulonglong2*>(&sR[kxo + 4]); \
    ulonglong2 I0 = *reinterpret_cast<const ulonglong2*>(&sI[kxo]); \
    ulonglong2 I1 = *reinterpret_cast<const ulonglong2*>(&sI[kxo + 4]); \
    ulonglong2 tp4 = *reinterpret_cast<const ulonglong2*>(&twp[p]); \
    ulonglong2 tn4 = *reinterpret_cast<const ulonglong2*>(&twn[p]); \
    fma2(CR[0], tn4.x, R0.x); fma2(CR[0], tn4.y, I0.x); \
    fma2(CR[1], tn4.x, R0.y); fma2(CR[1], tn4.y, I0.y); \
    fma2(CR[2], tn4.x, R1.x); fma2(CR[2], tn4.y, I1.x); \
    fma2(CR[3], tn4.x, R1.y); fma2(CR[3], tn4.y, I1.y); \
    fma2(CI[0], tp4.x, I0.x); fma2(CI[0], tp4.y, R0.x); \
    fma2(CI[1], tp4.x, I0.y); fma2(CI[1], tp4.y, R0.y); \
    fma2(CI[2], tp4.x, I1.x); fma2(CI[2], tp4.y, R1.x); \
    fma2(CI[3], tp4.x, I1.y); fma2(CI[3], tp4.y, R1.y); \
    p = (p + h0) & 255; kxo += OUTD; }

__global__ __launch_bounds__(256) void k4_inv_h() {
    __shared__ __align__(16) float sR[KXN*OUTD], sI[KXN*OUTD];
    __shared__ __align__(16) float4 twp[256], twn[256];
    const int t = threadIdx.x;
    twp[t] = g_tw4p[t]; twn[t] = g_tw4n[t];
    const int b = blockIdx.x, grp = b & 1, ky = (b >> 1) & 31, n = b >> 6;
    const float4* pR = reinterpret_cast<const float4*>(g_OmR + (size_t)(n*MD + ky)*KXN*OUTD);
    const float4* pI = reinterpret_cast<const float4*>(g_OmI + (size_t)(n*MD + ky)*KXN*OUTD);
#pragma unroll
    for (int it = 0; it < 4; it++) {
        reinterpret_cast<float4*>(sR)[t + 256*it] = pR[t + 256*it];
        reinterpret_cast<float4*>(sI)[t + 256*it] = pI[t + 256*it];
    }
    __syncthreads();
    const int o0 = (t & 7) * 8, h0 = grp*32 + (t >> 3);
    ull C0R[4], C0I[4], C1R[4], C1I[4], C2R[4], C2I[4], C3R[4], C3I[4];
#pragma unroll
    for (int j = 0; j < 4; j++) {
        C0R[j]=C0I[j]=C1R[j]=C1I[j]=0ull;
        C2R[j]=C2I[j]=C3R[j]=C3I[j]=0ull;
    }
#pragma unroll 1
    for (int kh = 0; kh < 2; kh++) {
        int p = kh ? ((224*h0) & 255) : 0;
        int kxo = (kh*32)*OUTD + o0;
#pragma unroll
        for (int kk = 0; kk < 32; kk += 4) {
            K4STEP(C0R, C0I)
            K4STEP(C1R, C1I)
            K4STEP(C2R, C2I)
            K4STEP(C3R, C3I)
        }
    }
    const ull NEG1 = splat2(-1.f);
    const ull FAC2 = splat2((ky == 0 ? 1.f : 2.f) * (1.f/256.f));
    float4 oR[4][2], oI[4][2];
#pragma unroll
    for (int j = 0; j < 4; j++) {
        ull ER = add2(C0R[j], C2R[j]), EI = add2(C0I[j], C2I[j]);
        ull FR = sub2(C0R[j], C2R[j], NEG1), FI = sub2(C0I[j], C2I[j], NEG1);
        ull GR = add2(C1R[j], C3R[j]), GI = add2(C1I[j], C3I[j]);
        ull HR = sub2(C1R[j], C3R[j], NEG1), HI = sub2(C1I[j], C3I[j], NEG1);
        ull YR[4] = { add2(ER, GR), sub2(FR, HI, NEG1), sub2(ER, GR, NEG1), add2(FR, HI) };
        ull YI[4] = { add2(EI, GI), add2(FI, HR), sub2(EI, GI, NEG1), sub2(FI, HR, NEG1) };
#pragma unroll
        for (int q = 0; q < 4; q++) {
            float2 vr = unpk(mul2(YR[q], FAC2));
            float2 vi = unpk(mul2(YI[q], FAC2));
            float* dR = reinterpret_cast<float*>(&oR[q][j >> 1]);
            float* dI = reinterpret_cast<float*>(&oI[q][j >> 1]);
            dR[(j & 1)*2] = vr.x; dR[(j & 1)*2 + 1] = vr.y;
            dI[(j & 1)*2] = vi.x; dI[(j & 1)*2 + 1] = vi.y;
        }
    }
#pragma unroll
    for (int q = 0; q < 4; q++) {
        size_t o = (size_t)((n*RR + h0 + 64*q)*MD + ky)*OUTD + o0;
        *reinterpret_cast<float4*>(&g_Y1R[o])     = oR[q][0];
        *reinterpret_cast<float4*>(&g_Y1R[o + 4]) = oR[q][1];
        *reinterpret_cast<float4*>(&g_Y1I[o])     = oI[q][0];
        *reinterpret_cast<float4*>(&g_Y1I[o + 4]) = oI[q][1];
    }
}

// ---------------- K5: radix-4 inverse w synthesis + residual + SiLU ---------
#define XPAD 68
__global__ __launch_bounds__(256) void k5_inv_w(const float* __restrict__ x,
                                                const float* __restrict__ res_w,
                                                const float* __restrict__ res_b,
                                                float* __restrict__ out) {
    extern __shared__ __align__(16) float xs[];       // [256][XPAD]
    __shared__ __align__(16) float YsR[MD*OUTD], YsI[MD*OUTD];
    __shared__ __align__(16) float rws[IND*OUTD];
    __shared__ __align__(16) float4 twp[256], twn[256];
    __shared__ __align__(16) float rbs[64];
    const int t = threadIdx.x, b = blockIdx.x, n = b >> 8, h = b & 255;
    twp[t] = g_tw4p[t];
    twn[t] = g_tw4n[t];
    const float4* xp = reinterpret_cast<const float4*>(x + (size_t)(n*RR + h)*RR*IND);
#pragma unroll
    for (int it = 0; it < 16; it++) {
        int j = t + 256*it;
        float4 v = xp[j];
        int w = j >> 4, c = j & 15;
        *reinterpret_cast<float4*>(&xs[w*XPAD + c*4]) = v;
    }
    const float4* yR4 = reinterpret_cast<const float4*>(g_Y1R + (size_t)(n*RR + h)*MD*OUTD);
    const float4* yI4 = reinterpret_cast<const float4*>(g_Y1I + (size_t)(n*RR + h)*MD*OUTD);
#pragma unroll
    for (int it = 0; it < 2; it++) {
        reinterpret_cast<float4*>(YsR)[t + 256*it] = yR4[t + 256*it];
        reinterpret_cast<float4*>(YsI)[t + 256*it] = yI4[t + 256*it];
    }
#pragma unroll
    for (int it = 0; it < 4; it++)
        reinterpret_cast<float4*>(rws)[t + 256*it] =
            reinterpret_cast<const float4*>(res_w)[t + 256*it];
    if (t < 64) rbs[t] = res_b[t];
    __syncthreads();

    const int ogrp = t & 3, w0 = t >> 2;
    const ull NEG1 = splat2(-1.f);
#pragma unroll 1
    for (int oh = 0; oh < 2; oh++) {
        const int o0 = oh*32 + ogrp*8;
        ull C0R[4], C2R[4], C1R[4], C1I[4], C3R[4], C3I[4];
#pragma unroll
        for (int j = 0; j < 4; j++) { C0R[j]=C2R[j]=C1R[j]=C1I[j]=C3R[j]=C3I[j]=0ull; }
        int p = 0;
#pragma unroll
        for (int kb = 0; kb < 8; kb++) {
            {
                const int ky = 4*kb;
                ulonglong2 yr0 = *reinterpret_cast<const ulonglong2*>(&YsR[ky*OUTD + o0]);
                ulonglong2 yr1 = *reinterpret_cast<const ulonglong2*>(&YsR[ky*OUTD + o0 + 4]);
                ulonglong2 yi0 = *reinterpret_cast<const ulonglong2*>(&YsI[ky*OUTD + o0]);
                ulonglong2 yi1 = *reinterpret_cast<const ulonglong2*>(&YsI[ky*OUTD + o0 + 4]);
                ulonglong2 tn4 = *reinterpret_cast<const ulonglong2*>(&twn[p]);
                fma2(C0R[0], tn4.x, yr0.x); fma2(C0R[0], tn4.y, yi0.x);
                fma2(C0R[1], tn4.x, yr0.y); fma2(C0R[1], tn4.y, yi0.y);
                fma2(C0R[2], tn4.x, yr1.x); fma2(C0R[2], tn4.y, yi1.x);
                fma2(C0R[3], tn4.x, yr1.y); fma2(C0R[3], tn4.y, yi1.y);
                p = (p + w0) & 255;
            }
            {
                const int ky = 4*kb + 1;
                ulonglong2 yr0 = *reinterpret_cast<const ulonglong2*>(&YsR[ky*OUTD + o0]);
                ulonglong2 yr1 = *reinterpret_cast<const ulonglong2*>(&YsR[ky*OUTD + o0 + 4]);
                ulonglong2 yi0 = *reinterpret_cast<const ulonglong2*>(&YsI[ky*OUTD + o0]);
                ulonglong2 yi1 = *reinterpret_cast<const ulonglong2*>(&YsI[ky*OUTD + o0 + 4]);
                ulonglong2 tn4 = *reinterpret_cast<const ulonglong2*>(&twn[p]);
                ulonglong2 tp4 = *reinterpret_cast<const ulonglong2*>(&twp[p]);
                fma2(C1R[0], tn4.x, yr0.x); fma2(C1R[0], tn4.y, yi0.x);
                fma2(C1R[1], tn4.x, yr0.y); fma2(C1R[1], tn4.y, yi0.y);
                fma2(C1R[2], tn4.x, yr1.x); fma2(C1R[2], tn4.y, yi1.x);
                fma2(C1R[3], tn4.x, yr1.y); fma2(C1R[3], tn4.y, yi1.y);
                fma2(C1I[0], tp4.x, yi0.x); fma2(C1I[0], tp4.y, yr0.x);
                fma2(C1I[1], tp4.x, yi0.y); fma2(C1I[1], tp4.y, yr0.y);
                fma2(C1I[2], tp4.x, yi1.x); fma2(C1I[2], tp4.y, yr1.x);
                fma2(C1I[3], tp4.x, yi1.y); fma2(C1I[3], tp4.y, yr1.y);
                p = (p + w0) & 255;
            }
            {
                const int ky = 4*kb + 2;
                ulonglong2 yr0 = *reinterpret_cast<const ulonglong2*>(&YsR[ky*OUTD + o0]);
                ulonglong2 yr1 = *reinterpret_cast<const ulonglong2*>(&YsR[ky*OUTD + o0 + 4]);
                ulonglong2 yi0 = *reinterpret_cast<const ulonglong2*>(&YsI[ky*OUTD + o0]);
                ulonglong2 yi1 = *reinterpret_cast<const ulonglong2*>(&YsI[ky*OUTD + o0 + 4]);
                ulonglong2 tn4 = *reinterpret_cast<const ulonglong2*>(&twn[p]);
                fma2(C2R[0], tn4.x, yr0.x); fma2(C2R[0], tn4.y, yi0.x);
                fma2(C2R[1], tn4.x, yr0.y); fma2(C2R[1], tn4.y, yi0.y);
                fma2(C2R[2], tn4.x, yr1.x); fma2(C2R[2], tn4.y, yi1.x);
                fma2(C2R[3], tn4.x, yr1.y); fma2(C2R[3], tn4.y, yi1.y);
                p = (p + w0) & 255;
            }
            {
                const int ky = 4*kb + 3;
                ulonglong2 yr0 = *reinterpret_cast<const ulonglong2*>(&YsR[ky*OUTD + o0]);
                ulonglong2 yr1 = *reinterpret_cast<const ulonglong2*>(&YsR[ky*OUTD + o0 + 4]);
                ulonglong2 yi0 = *reinterpret_cast<const ulonglong2*>(&YsI[ky*OUTD + o0]);
                ulonglong2 yi1 = *reinterpret_cast<const ulonglong2*>(&YsI[ky*OUTD + o0 + 4]);
                ulonglong2 tn4 = *reinterpret_cast<const ulonglong2*>(&twn[p]);
                ulonglong2 tp4 = *reinterpret_cast<const ulonglong2*>(&twp[p]);
                fma2(C3R[0], tn4.x, yr0.x); fma2(C3R[0], tn4.y, yi0.x);
                fma2(C3R[1], tn4.x, yr0.y); fma2(C3R[1], tn4.y, yi0.y);
                fma2(C3R[2], tn4.x, yr1.x); fma2(C3R[2], tn4.y, yi1.x);
                fma2(C3R[3], tn4.x, yr1.y); fma2(C3R[3], tn4.y, yi1.y);
                fma2(C3I[0], tp4.x, yi0.x); fma2(C3I[0], tp4.y, yr0.x);
                fma2(C3I[1], tp4.x, yi0.y); fma2(C3I[1], tp4.y, yr0.y);
                fma2(C3I[2], tp4.x, yi1.x); fma2(C3I[2], tp4.y, yr1.x);
                fma2(C3I[3], tp4.x, yi1.y); fma2(C3I[3], tp4.y, yr1.y);
                p = (p + w0) & 255;
            }
        }
        ull y[4][4];
        {
            ulonglong2 b01 = *reinterpret_cast<const ulonglong2*>(&rbs[o0]);
            ulonglong2 b23 = *reinterpret_cast<const ulonglong2*>(&rbs[o0 + 4]);
            ull bias[4] = {b01.x, b01.y, b23.x, b23.y};
#pragma unroll
            for (int j = 0; j < 4; j++) {
                ull e  = add2(C0R[j], C2R[j]);
                ull f  = sub2(C0R[j], C2R[j], NEG1);
                ull g  = add2(C1R[j], C3R[j]);
                ull hh = sub2(C3I[j], C1I[j], NEG1);
                y[0][j] = add2(add2(e, g),  bias[j]);
                y[2][j] = add2(sub2(e, g,  NEG1), bias[j]);
                y[1][j] = add2(add2(f, hh), bias[j]);
                y[3][j] = add2(sub2(f, hh, NEG1), bias[j]);
            }
        }
        for (int i = 0; i < IND; i++) {
            ulonglong2 r01 = *reinterpret_cast<const ulonglong2*>(&rws[i*OUTD + o0]);
            ulonglong2 r23 = *reinterpret_cast<const ulonglong2*>(&rws[i*OUTD + o0 + 4]);
#pragma unroll
            for (int q = 0; q < 4; q++) {
                ull sx = splat2(xs[(w0 + 64*q)*XPAD + i]);
                fma2(y[q][0], sx, r01.x); fma2(y[q][1], sx, r01.y);
                fma2(y[q][2], sx, r23.x); fma2(y[q][3], sx, r23.y);
            }
        }
#pragma unroll
        for (int q = 0; q < 4; q++) {
            float4 v4[2];
#pragma unroll
            for (int c = 0; c < 4; c++) {
                float2 v = unpk(y[q][c]);
                v.x = v.x / (1.f + __expf(-v.x));
                v.y = v.y / (1.f + __expf(-v.y));
                reinterpret_cast<float2*>(v4)[c] = v;
            }
            size_t o = (size_t)((n*RR + h)*RR + (w0 + 64*q))*OUTD + o0;
            *reinterpret_cast<float4*>(&out[o])     = v4[0];
            *reinterpret_cast<float4*>(&out[o + 4]) = v4[1];
        }
    }
}

// ---------------- launch ----------------------------------------------------
extern "C" void kernel_launch(void* const* d_in, const int* in_sizes, int n_in,
                              void* d_out, int out_size) {
    const float* x   = (const float*)d_in[0];
    const float* w0  = (const float*)d_in[1];
    const float* w1  = (const float*)d_in[2];
    const float* rsw = (const float*)d_in[3];
    const float* rsb = (const float*)d_in[4];
    float* out = (float*)d_out;

    cudaFuncSetAttribute(k1_fwd_w, cudaFuncAttributeMaxDynamicSharedMemorySize, 65536);
    cudaFuncSetAttribute(k5_inv_w, cudaFuncAttributeMaxDynamicSharedMemorySize, RR*XPAD*4);

    k_init_tw<<<1, 256>>>();
    k1_fwd_w<<<NB*RR, 128, 65536>>>(x);
    k2_fwd_h<<<NB*MD*2, 256>>>();
    k3_mix<<<KXN*MD, 256>>>(w0, w1);
    k4_inv_h<<<NB*MD*2, 256>>>();
    k5_inv_w<<<NB*RR, 256, RR*XPAD*4>>>(x, rsw, rsb, out);
}